// round 3
// baseline (speedup 1.0000x reference)
#include <cuda_runtime.h>
#include <math.h>

#define B_ 64
#define N_ 512
#define E_ 128
#define H_ 8
#define D_ 16

// ---------------- scratch (no allocations allowed) ----------------
__device__ float g_K [B_ * N_ * 128];
__device__ float g_V [B_ * N_ * 128];
__device__ float g_Q [B_ * N_ * 128];
__device__ float g_MH[B_ * N_ * 128];

#define WT_STRIDE 132   // padded stride for transposed weight tiles in smem

// =====================================================================
// Generic: C[row0:row0+64, 0:128] (+)= A[row0:row0+64, 0:128] @ W[128,128]^T
// W is [out=128][e=128] row-major (so C = A @ W^T).
// =====================================================================
template <bool ACCUM>
__global__ __launch_bounds__(256) void gemm128_kernel(
    const float* __restrict__ A, const float* __restrict__ W, float* __restrict__ C)
{
    extern __shared__ float sm[];
    float* sa  = sm;            // 64*128 floats
    float* swt = sm + 64 * 128; // [e][o], stride WT_STRIDE (128*132 floats)
    const int tid  = threadIdx.x;
    const int row0 = blockIdx.x * 64;

    // A tile (coalesced float4)
    {
        const float4* Ag  = (const float4*)(A + row0 * 128);
        float4*       sa4 = (float4*)sa;
        #pragma unroll
        for (int i = 0; i < 8; i++) sa4[tid + 256 * i] = Ag[tid + 256 * i];
    }
    // W, transposed into smem: swt[e][o] = W[o][e]
    {
        const float4* Wg = (const float4*)W;
        #pragma unroll
        for (int i = 0; i < 16; i++) {
            int    f  = tid + 256 * i;      // 4096 float4s
            int    o  = f >> 5;
            int    e4 = (f & 31) << 2;
            float4 w  = Wg[f];
            swt[(e4 + 0) * WT_STRIDE + o] = w.x;
            swt[(e4 + 1) * WT_STRIDE + o] = w.y;
            swt[(e4 + 2) * WT_STRIDE + o] = w.z;
            swt[(e4 + 3) * WT_STRIDE + o] = w.w;
        }
    }
    __syncthreads();

    const int ty = tid >> 4, tx = tid & 15;
    const int r0 = ty * 4, c0 = tx * 8;
    float acc[4][8];
    #pragma unroll
    for (int i = 0; i < 4; i++)
        #pragma unroll
        for (int j = 0; j < 8; j++) acc[i][j] = 0.f;

    #pragma unroll 4
    for (int e = 0; e < 128; e++) {
        float4 w0 = *(const float4*)&swt[e * WT_STRIDE + c0];
        float4 w1 = *(const float4*)&swt[e * WT_STRIDE + c0 + 4];
        float  wv[8] = {w0.x, w0.y, w0.z, w0.w, w1.x, w1.y, w1.z, w1.w};
        #pragma unroll
        for (int i = 0; i < 4; i++) {
            float a = sa[(r0 + i) * 128 + e];
            #pragma unroll
            for (int j = 0; j < 8; j++) acc[i][j] = fmaf(a, wv[j], acc[i][j]);
        }
    }

    #pragma unroll
    for (int i = 0; i < 4; i++) {
        float* Crow = C + (row0 + r0 + i) * 128 + c0;
        float4 o0 = make_float4(acc[i][0], acc[i][1], acc[i][2], acc[i][3]);
        float4 o1 = make_float4(acc[i][4], acc[i][5], acc[i][6], acc[i][7]);
        if (ACCUM) {
            float4 c0v = *(const float4*)&Crow[0];
            float4 c1v = *(const float4*)&Crow[4];
            o0.x += c0v.x; o0.y += c0v.y; o0.z += c0v.z; o0.w += c0v.w;
            o1.x += c1v.x; o1.y += c1v.y; o1.z += c1v.z; o1.w += c1v.w;
        }
        *(float4*)&Crow[0] = o0;
        *(float4*)&Crow[4] = o1;
    }
}

// =====================================================================
// Attention (flash-style online softmax) + output projection -> g_MH
// Grid: (N/64, B). 256 threads = 8 warps; warp = head; lane -> rows l, l+32.
// =====================================================================
__global__ __launch_bounds__(256) void attn_kernel(
    const float* __restrict__ mask, const float* __restrict__ Wc,
    const float* __restrict__ bc)
{
    extern __shared__ float sm[];
    // phase 1 layout (floats):
    float* qs = sm;          // [0,     8192)
    float* ks = sm + 8192;   // [8192, 16384)
    float* vs = sm + 16384;  // [16384,24576)
    float* ms = sm + 24576;  // 64*65 = 4160 -> ends 28736
    // phase 2 layout (overlaps phase-1 regions that are dead by then):
    float* wct  = sm;          // 128*132 = 16896 floats  [0, 16896)
    float* outs = sm + 16896;  // 64*128  =  8192 floats  [16896, 25088)
    float* sbc  = sm + 25088;  // 128 floats

    const int tid  = threadIdx.x;
    const int lane = tid & 31, h = tid >> 5;
    const int b = blockIdx.y, n0 = blockIdx.x * 64;

    // load Q tile
    {
        const float4* Qg = (const float4*)(g_Q + (b * N_ + n0) * 128);
        float4*       q4 = (float4*)qs;
        #pragma unroll
        for (int i = 0; i < 8; i++) q4[tid + 256 * i] = Qg[tid + 256 * i];
    }
    __syncthreads();

    float q0r[16], q1r[16];
    #pragma unroll
    for (int k = 0; k < 16; k += 4) {
        *(float4*)&q0r[k] = *(const float4*)&qs[lane * 128 + h * 16 + k];
        *(float4*)&q1r[k] = *(const float4*)&qs[(lane + 32) * 128 + h * 16 + k];
    }

    float acc0[16], acc1[16];
    #pragma unroll
    for (int k = 0; k < 16; k++) { acc0[k] = 0.f; acc1[k] = 0.f; }
    float mx0 = -1e30f, mx1 = -1e30f, sum0 = 0.f, sum1 = 0.f;

    for (int c = 0; c < 8; c++) {
        const int m0 = c * 64;
        __syncthreads();
        {
            const float4* Kg = (const float4*)(g_K + (b * N_ + m0) * 128);
            const float4* Vg = (const float4*)(g_V + (b * N_ + m0) * 128);
            float4* k4 = (float4*)ks;
            float4* v4 = (float4*)vs;
            #pragma unroll
            for (int i = 0; i < 8; i++) {
                k4[tid + 256 * i] = Kg[tid + 256 * i];
                v4[tid + 256 * i] = Vg[tid + 256 * i];
            }
            const float* Mg = mask + (b * N_ + n0) * N_ + m0;
            #pragma unroll
            for (int i = 0; i < 16; i++) {
                int f = tid + 256 * i;       // 4096 = 64*64
                int r = f >> 6, m = f & 63;
                ms[r * 65 + m] = Mg[r * N_ + m];
            }
        }
        __syncthreads();

        for (int m = 0; m < 64; m++) {
            float kr[16];
            const float* kp = ks + m * 128 + h * 16;
            #pragma unroll
            for (int k = 0; k < 16; k += 4) *(float4*)&kr[k] = *(const float4*)&kp[k];
            float s0 = 0.f, s1 = 0.f;
            #pragma unroll
            for (int k = 0; k < 16; k++) {
                s0 = fmaf(q0r[k], kr[k], s0);
                s1 = fmaf(q1r[k], kr[k], s1);
            }
            s0 = s0 * 0.25f + ms[lane * 65 + m];
            s1 = s1 * 0.25f + ms[(lane + 32) * 65 + m];

            float vr[16];
            const float* vp = vs + m * 128 + h * 16;
            #pragma unroll
            for (int k = 0; k < 16; k += 4) *(float4*)&vr[k] = *(const float4*)&vp[k];

            float p0, p1;
            if (s0 > mx0) {
                float corr = __expf(mx0 - s0);
                sum0 = sum0 * corr + 1.f;
                #pragma unroll
                for (int k = 0; k < 16; k++) acc0[k] *= corr;
                mx0 = s0; p0 = 1.f;
            } else {
                p0 = __expf(s0 - mx0); sum0 += p0;
            }
            #pragma unroll
            for (int k = 0; k < 16; k++) acc0[k] = fmaf(p0, vr[k], acc0[k]);

            if (s1 > mx1) {
                float corr = __expf(mx1 - s1);
                sum1 = sum1 * corr + 1.f;
                #pragma unroll
                for (int k = 0; k < 16; k++) acc1[k] *= corr;
                mx1 = s1; p1 = 1.f;
            } else {
                p1 = __expf(s1 - mx1); sum1 += p1;
            }
            #pragma unroll
            for (int k = 0; k < 16; k++) acc1[k] = fmaf(p1, vr[k], acc1[k]);
        }
    }

    __syncthreads();   // everyone done reading ks/vs/ms/qs before overwrite

    // normalize + stage attention output: outs[row][h*16+d]
    {
        float inv0 = __fdividef(1.f, sum0);
        float inv1 = __fdividef(1.f, sum1);
        #pragma unroll
        for (int k = 0; k < 16; k++) { acc0[k] *= inv0; acc1[k] *= inv1; }
        #pragma unroll
        for (int k = 0; k < 16; k += 4) {
            *(float4*)&outs[lane * 128 + h * 16 + k]        = *(float4*)&acc0[k];
            *(float4*)&outs[(lane + 32) * 128 + h * 16 + k] = *(float4*)&acc1[k];
        }
    }
    // load Wc transposed + bc
    {
        const float4* Wg = (const float4*)Wc;
        #pragma unroll
        for (int i = 0; i < 16; i++) {
            int    f  = tid + 256 * i;
            int    o  = f >> 5;            // E row of Wc
            int    e4 = (f & 31) << 2;     // HD index (contraction)
            float4 w  = Wg[f];
            wct[(e4 + 0) * WT_STRIDE + o] = w.x;
            wct[(e4 + 1) * WT_STRIDE + o] = w.y;
            wct[(e4 + 2) * WT_STRIDE + o] = w.z;
            wct[(e4 + 3) * WT_STRIDE + o] = w.w;
        }
        if (tid < 128) sbc[tid] = bc[tid];
    }
    __syncthreads();

    // mh = outs @ Wc^T + bc
    const int ty = tid >> 4, tx = tid & 15;
    const int r0 = ty * 4, c0 = tx * 8;
    float macc[4][8];
    #pragma unroll
    for (int i = 0; i < 4; i++)
        #pragma unroll
        for (int j = 0; j < 8; j++) macc[i][j] = 0.f;

    #pragma unroll 4
    for (int e = 0; e < 128; e++) {
        float4 w0 = *(const float4*)&wct[e * WT_STRIDE + c0];
        float4 w1 = *(const float4*)&wct[e * WT_STRIDE + c0 + 4];
        float  wv[8] = {w0.x, w0.y, w0.z, w0.w, w1.x, w1.y, w1.z, w1.w};
        #pragma unroll
        for (int i = 0; i < 4; i++) {
            float a = outs[(r0 + i) * 128 + e];
            #pragma unroll
            for (int j = 0; j < 8; j++) macc[i][j] = fmaf(a, wv[j], macc[i][j]);
        }
    }
    #pragma unroll
    for (int i = 0; i < 4; i++) {
        float* dst = g_MH + (b * N_ + n0 + r0 + i) * 128 + c0;
        float4 o0 = make_float4(macc[i][0] + sbc[c0 + 0], macc[i][1] + sbc[c0 + 1],
                                macc[i][2] + sbc[c0 + 2], macc[i][3] + sbc[c0 + 3]);
        float4 o1 = make_float4(macc[i][4] + sbc[c0 + 4], macc[i][5] + sbc[c0 + 5],
                                macc[i][6] + sbc[c0 + 6], macc[i][7] + sbc[c0 + 7]);
        *(float4*)&dst[0] = o0;
        *(float4*)&dst[4] = o1;
    }
}

// =====================================================================
// Pointer scores: s = 10*tanh((MH @ enc^T)/sqrt(E)) + mask ; row-softmax.
// Grid: (N/64, B). 256 threads.
// =====================================================================
__global__ __launch_bounds__(256) void pointer_kernel(
    const float* __restrict__ enc, const float* __restrict__ mask,
    float* __restrict__ out)
{
    extern __shared__ float sm[];
    float* smh  = sm;           // 64*128 = 8192 floats
    float* enct = sm + 8192;    // 128*68 = 8704 floats (transposed enc chunk)
    float* sbuf = sm + 16896;   // 64*516 = 33024 floats
    const int tid = threadIdx.x;
    const int b = blockIdx.y, n0 = blockIdx.x * 64;

    {
        const float4* Mh  = (const float4*)(g_MH + (b * N_ + n0) * 128);
        float4*       mh4 = (float4*)smh;
        #pragma unroll
        for (int i = 0; i < 8; i++) mh4[tid + 256 * i] = Mh[tid + 256 * i];
    }

    const int ty = tid >> 4, tx = tid & 15;
    const int r0 = ty * 4, m0l = tx * 4;

    for (int c = 0; c < 8; c++) {
        __syncthreads();
        {
            const float4* Eg = (const float4*)(enc + (b * N_ + c * 64) * 128);
            #pragma unroll
            for (int i = 0; i < 8; i++) {
                int    f  = tid + 256 * i;   // 2048 float4
                int    m  = f >> 5;
                int    e4 = (f & 31) << 2;
                float4 v  = Eg[f];
                enct[(e4 + 0) * 68 + m] = v.x;
                enct[(e4 + 1) * 68 + m] = v.y;
                enct[(e4 + 2) * 68 + m] = v.z;
                enct[(e4 + 3) * 68 + m] = v.w;
            }
        }
        __syncthreads();

        float acc[4][4];
        #pragma unroll
        for (int i = 0; i < 4; i++)
            #pragma unroll
            for (int j = 0; j < 4; j++) acc[i][j] = 0.f;

        #pragma unroll 4
        for (int e = 0; e < 128; e++) {
            float4 ev = *(const float4*)&enct[e * 68 + m0l];
            #pragma unroll
            for (int i = 0; i < 4; i++) {
                float a = smh[(r0 + i) * 128 + e];
                acc[i][0] = fmaf(a, ev.x, acc[i][0]);
                acc[i][1] = fmaf(a, ev.y, acc[i][1]);
                acc[i][2] = fmaf(a, ev.z, acc[i][2]);
                acc[i][3] = fmaf(a, ev.w, acc[i][3]);
            }
        }

        const float* Mg = mask + (b * N_ + n0) * N_ + c * 64;
        #pragma unroll
        for (int i = 0; i < 4; i++) {
            float4 mv = *(const float4*)&Mg[(r0 + i) * N_ + m0l];
            float  mk[4] = {mv.x, mv.y, mv.z, mv.w};
            float  res[4];
            #pragma unroll
            for (int j = 0; j < 4; j++) {
                float z  = acc[i][j] * 0.08838834764831845f; // 1/sqrt(128)
                z        = fminf(fmaxf(z, -15.f), 15.f);
                float e2 = __expf(2.f * z);
                float t  = __fdividef(e2 - 1.f, e2 + 1.f);
                res[j]   = 10.f * t + mk[j];
            }
            *(float4*)&sbuf[(r0 + i) * 516 + c * 64 + m0l] =
                make_float4(res[0], res[1], res[2], res[3]);
        }
    }
    __syncthreads();

    // row softmax: warp w handles rows w*8 .. w*8+7
    const int lane = tid & 31, w = tid >> 5;
    for (int rr = 0; rr < 8; rr++) {
        const int r    = w * 8 + rr;
        float*    srow = sbuf + r * 516;
        float     mx   = -1e30f;
        #pragma unroll
        for (int j = lane; j < 512; j += 32) mx = fmaxf(mx, srow[j]);
        #pragma unroll
        for (int off = 16; off >= 1; off >>= 1)
            mx = fmaxf(mx, __shfl_xor_sync(0xffffffffu, mx, off));
        float sum = 0.f;
        #pragma unroll
        for (int j = lane; j < 512; j += 32) {
            float p = __expf(srow[j] - mx);
            srow[j] = p;
            sum += p;
        }
        #pragma unroll
        for (int off = 16; off >= 1; off >>= 1)
            sum += __shfl_xor_sync(0xffffffffu, sum, off);
        float  inv  = __fdividef(1.f, sum);
        float* orow = out + (b * N_ + n0 + r) * N_;
        #pragma unroll
        for (int j = lane; j < 512; j += 32) orow[j] = srow[j] * inv;
    }
}

// =====================================================================
extern "C" void kernel_launch(void* const* d_in, const int* in_sizes, int n_in,
                              void* d_out, int out_size)
{
    const float* enc       = (const float*)d_in[0];
    const float* first_row = (const float*)d_in[1];
    const float* q0        = (const float*)d_in[2];
    const float* mask      = (const float*)d_in[3];
    const float* Wq0       = (const float*)d_in[4];
    const float* Wq1       = (const float*)d_in[5];
    const float* Wk        = (const float*)d_in[6];
    const float* Wv        = (const float*)d_in[7];
    const float* Wc        = (const float*)d_in[8];
    const float* bc        = (const float*)d_in[9];
    float*       out       = (float*)d_out;

    float *pK, *pV, *pQ;
    cudaGetSymbolAddress((void**)&pK, g_K);
    cudaGetSymbolAddress((void**)&pV, g_V);
    cudaGetSymbolAddress((void**)&pQ, g_Q);

    const int SMEM_G = (64 * 128 + 128 * WT_STRIDE) * 4;            // 100352
    const int SMEM_A = (8192 + 8192 + 8192 + 64 * 65) * 4;          // 114944
    const int SMEM_P = (8192 + 8704 + 33024) * 4;                   // 199680

    cudaFuncSetAttribute(gemm128_kernel<false>,
                         cudaFuncAttributeMaxDynamicSharedMemorySize, SMEM_G);
    cudaFuncSetAttribute(gemm128_kernel<true>,
                         cudaFuncAttributeMaxDynamicSharedMemorySize, SMEM_G);
    cudaFuncSetAttribute(attn_kernel,
                         cudaFuncAttributeMaxDynamicSharedMemorySize, SMEM_A);
    cudaFuncSetAttribute(pointer_kernel,
                         cudaFuncAttributeMaxDynamicSharedMemorySize, SMEM_P);

    // Projections: Q = first_row@Wq1^T + q0@Wq0^T ; K = enc@Wk^T ; V = enc@Wv^T
    gemm128_kernel<false><<<512, 256, SMEM_G>>>(first_row, Wq1, pQ);
    gemm128_kernel<true ><<<512, 256, SMEM_G>>>(q0,        Wq0, pQ);
    gemm128_kernel<false><<<512, 256, SMEM_G>>>(enc,       Wk,  pK);
    gemm128_kernel<false><<<512, 256, SMEM_G>>>(enc,       Wv,  pV);

    attn_kernel   <<<dim3(8, B_), 256, SMEM_A>>>(mask, Wc, bc);
    pointer_kernel<<<dim3(8, B_), 256, SMEM_P>>>(enc, mask, out);
}

// round 4
// speedup vs baseline: 1.0736x; 1.0736x over previous
#include <cuda_runtime.h>
#include <math.h>

#define B_ 64
#define N_ 512
#define E_ 128
#define H_ 8
#define D_ 16

typedef unsigned long long u64;

// ---------------- scratch (no allocations allowed) ----------------
__device__ float g_K [B_ * N_ * 128];
__device__ float g_V [B_ * N_ * 128];
__device__ float g_Q [B_ * N_ * 128];
__device__ float g_MH[B_ * N_ * 128];

#define LOG2E 1.4426950408889634f

// ---------------- f32x2 helpers (sm_100+ packed fp32) ----------------
__device__ __forceinline__ void ffma2(u64& d, u64 a, u64 b) {
    asm("fma.rn.f32x2 %0, %1, %2, %0;" : "+l"(d) : "l"(a), "l"(b));
}
__device__ __forceinline__ u64 mul2(u64 a, u64 b) {
    u64 r; asm("mul.rn.f32x2 %0, %1, %2;" : "=l"(r) : "l"(a), "l"(b)); return r;
}
__device__ __forceinline__ u64 add2(u64 a, u64 b) {
    u64 r; asm("add.rn.f32x2 %0, %1, %2;" : "=l"(r) : "l"(a), "l"(b)); return r;
}
__device__ __forceinline__ u64 splat2(float x) {
    u64 r; asm("mov.b64 %0, {%1, %1};" : "=l"(r) : "f"(x)); return r;
}
__device__ __forceinline__ float2 unpack2(u64 v) {
    float2 f; asm("mov.b64 {%0, %1}, %2;" : "=f"(f.x), "=f"(f.y) : "l"(v)); return f;
}
__device__ __forceinline__ float ex2f(float x) {
    float r; asm("ex2.approx.ftz.f32 %0, %1;" : "=f"(r) : "f"(x)); return r;
}

// W^T smem layout: two half-arrays so each lane's 16B chunk is contiguous
// swL[e][g*4 + j] = W[g*8 + j][e]      (j = 0..3)
// swH[e][g*4 + j] = W[g*8 + 4 + j][e]  (j = 0..3)
// -> lanes (g = tx) read stride-16B contiguous: conflict-free LDS.128.
__device__ __forceinline__ void stage_wt(const float* __restrict__ W,
                                         float* swL, float* swH, int tid)
{
    const float4* Wg = (const float4*)W;
    #pragma unroll
    for (int i = 0; i < 16; i++) {
        int    f  = tid + 256 * i;      // 4096 float4s over [o=128][e=128]
        int    o  = f >> 5;
        int    e4 = (f & 31) << 2;
        float4 w  = Wg[f];
        int    g  = o >> 3, j = o & 7;
        float* base = (j < 4) ? swL : swH;
        int    jj   = g * 4 + (j & 3);
        base[(e4 + 0) * 64 + jj] = w.x;
        base[(e4 + 1) * 64 + jj] = w.y;
        base[(e4 + 2) * 64 + jj] = w.z;
        base[(e4 + 3) * 64 + jj] = w.w;
    }
}

// Core 64x128 @ 128x128^T microkernel body (A in smem row-major, W in swL/swH).
// Thread (ty=tid>>4, tx=tid&15): rows ty*4..+3, cols tx*8..+7 as 4 f32x2 pairs.
__device__ __forceinline__ void mm_body(const float* sa, const float* swL,
                                        const float* swH, int r0, int tx,
                                        u64 acc[4][4])
{
    #pragma unroll 2
    for (int e4 = 0; e4 < 128; e4 += 4) {
        float4 av[4];
        #pragma unroll
        for (int i = 0; i < 4; i++) av[i] = *(const float4*)&sa[(r0 + i) * 128 + e4];
        ulonglong2 wl[4], wh[4];
        #pragma unroll
        for (int e = 0; e < 4; e++) {
            wl[e] = *(const ulonglong2*)&swL[(e4 + e) * 64 + tx * 4];
            wh[e] = *(const ulonglong2*)&swH[(e4 + e) * 64 + tx * 4];
        }
        #pragma unroll
        for (int e = 0; e < 4; e++) {
            #pragma unroll
            for (int i = 0; i < 4; i++) {
                u64 as = splat2(((const float*)&av[i])[e]);
                ffma2(acc[i][0], as, wl[e].x);
                ffma2(acc[i][1], as, wl[e].y);
                ffma2(acc[i][2], as, wh[e].x);
                ffma2(acc[i][3], as, wh[e].y);
            }
        }
    }
}

// =====================================================================
// C[row0:+64, 0:128] (+)= A[row0:+64, 0:128] @ W[128,128]^T
// =====================================================================
template <bool ACCUM>
__global__ __launch_bounds__(256, 2) void gemm128_kernel(
    const float* __restrict__ A, const float* __restrict__ W, float* __restrict__ C)
{
    extern __shared__ float sm[];
    float* sa  = sm;            // 8192
    float* swL = sm + 8192;     // 128*64
    float* swH = sm + 16384;    // 128*64
    const int tid  = threadIdx.x;
    const int row0 = blockIdx.x * 64;

    {
        const float4* Ag  = (const float4*)(A + row0 * 128);
        float4*       sa4 = (float4*)sa;
        #pragma unroll
        for (int i = 0; i < 8; i++) sa4[tid + 256 * i] = Ag[tid + 256 * i];
    }
    stage_wt(W, swL, swH, tid);
    __syncthreads();

    const int ty = tid >> 4, tx = tid & 15;
    const int r0 = ty * 4, c0 = tx * 8;
    u64 acc[4][4];
    #pragma unroll
    for (int i = 0; i < 4; i++)
        #pragma unroll
        for (int j = 0; j < 4; j++) acc[i][j] = 0ull;

    mm_body(sa, swL, swH, r0, tx, acc);

    #pragma unroll
    for (int i = 0; i < 4; i++) {
        float* Crow = C + (row0 + r0 + i) * 128 + c0;
        if (ACCUM) {
            ulonglong2 o0 = *(const ulonglong2*)&Crow[0];
            ulonglong2 o1 = *(const ulonglong2*)&Crow[4];
            acc[i][0] = add2(acc[i][0], o0.x);
            acc[i][1] = add2(acc[i][1], o0.y);
            acc[i][2] = add2(acc[i][2], o1.x);
            acc[i][3] = add2(acc[i][3], o1.y);
        }
        ulonglong2 s0, s1;
        s0.x = acc[i][0]; s0.y = acc[i][1];
        s1.x = acc[i][2]; s1.y = acc[i][3];
        *(ulonglong2*)&Crow[0] = s0;
        *(ulonglong2*)&Crow[4] = s1;
    }
}

// =====================================================================
// Attention (online softmax, log2 domain) + output projection -> g_MH
// Grid: (N/64, B). 256 threads = 8 warps; warp = head; lane -> rows l, l+32.
// =====================================================================
__global__ __launch_bounds__(256, 2) void attn_kernel(
    const float* __restrict__ mask, const float* __restrict__ Wc,
    const float* __restrict__ bc)
{
    extern __shared__ float sm[];
    // phase 1:
    float* ks = sm;            // [0, 8192)
    float* vs = sm + 8192;     // [8192, 16384)
    float* ms = sm + 16384;    // 64*65 -> [16384, 20544)
    // phase 2 (after final sync, reuses everything):
    float* wcL  = sm;          // [0, 8192)
    float* wcH  = sm + 8192;   // [8192, 16384)
    float* outs = sm + 16384;  // [16384, 24576)
    float* sbc  = sm + 24576;  // 128

    const int tid  = threadIdx.x;
    const int lane = tid & 31, h = tid >> 5;
    const int b = blockIdx.y, n0 = blockIdx.x * 64;

    // q rows (lane, lane+32) straight from gmem, pre-scaled by 0.25*log2e
    u64 q0p[8], q1p[8];
    {
        const u64* Qg0 = (const u64*)(g_Q + (b * N_ + n0 + lane) * 128 + h * 16);
        const u64* Qg1 = (const u64*)(g_Q + (b * N_ + n0 + lane + 32) * 128 + h * 16);
        const u64 cs = splat2(0.25f * LOG2E);
        #pragma unroll
        for (int j = 0; j < 8; j++) {
            q0p[j] = mul2(Qg0[j], cs);
            q1p[j] = mul2(Qg1[j], cs);
        }
    }

    u64 accp0[8], accp1[8];
    #pragma unroll
    for (int j = 0; j < 8; j++) { accp0[j] = 0ull; accp1[j] = 0ull; }
    float mx0 = -1e30f, mx1 = -1e30f, sum0 = 0.f, sum1 = 0.f;

    for (int c = 0; c < 8; c++) {
        const int m0 = c * 64;
        __syncthreads();
        {
            const float4* Kg = (const float4*)(g_K + (b * N_ + m0) * 128);
            const float4* Vg = (const float4*)(g_V + (b * N_ + m0) * 128);
            float4* k4 = (float4*)ks;
            float4* v4 = (float4*)vs;
            #pragma unroll
            for (int i = 0; i < 8; i++) {
                k4[tid + 256 * i] = Kg[tid + 256 * i];
                v4[tid + 256 * i] = Vg[tid + 256 * i];
            }
            const float* Mg = mask + (b * N_ + n0) * N_ + m0;
            #pragma unroll
            for (int i = 0; i < 16; i++) {
                int f = tid + 256 * i;       // 4096 = 64*64
                int r = f >> 6, m = f & 63;
                ms[r * 65 + m] = Mg[r * N_ + m] * LOG2E;
            }
        }
        __syncthreads();

        for (int m = 0; m < 64; m++) {
            // QK dot (packed over d), all lanes broadcast-read same k/v row
            const ulonglong2* kp = (const ulonglong2*)(ks + m * 128 + h * 16);
            u64 kr[8];
            #pragma unroll
            for (int j = 0; j < 4; j++) {
                ulonglong2 t = kp[j]; kr[2 * j] = t.x; kr[2 * j + 1] = t.y;
            }
            u64 d0 = 0ull, d1 = 0ull;
            #pragma unroll
            for (int j = 0; j < 8; j++) {
                ffma2(d0, q0p[j], kr[j]);
                ffma2(d1, q1p[j], kr[j]);
            }
            float2 f0 = unpack2(d0), f1 = unpack2(d1);
            float s0 = f0.x + f0.y + ms[lane * 65 + m];
            float s1 = f1.x + f1.y + ms[(lane + 32) * 65 + m];

            const ulonglong2* vp = (const ulonglong2*)(vs + m * 128 + h * 16);
            u64 vr[8];
            #pragma unroll
            for (int j = 0; j < 4; j++) {
                ulonglong2 t = vp[j]; vr[2 * j] = t.x; vr[2 * j + 1] = t.y;
            }

            float p0, p1;
            if (s0 > mx0) {
                float corr = ex2f(mx0 - s0);
                u64   cs   = splat2(corr);
                sum0 = sum0 * corr + 1.f;
                #pragma unroll
                for (int j = 0; j < 8; j++) accp0[j] = mul2(accp0[j], cs);
                mx0 = s0; p0 = 1.f;
            } else {
                p0 = ex2f(s0 - mx0); sum0 += p0;
            }
            {
                u64 ps = splat2(p0);
                #pragma unroll
                for (int j = 0; j < 8; j++) ffma2(accp0[j], ps, vr[j]);
            }

            if (s1 > mx1) {
                float corr = ex2f(mx1 - s1);
                u64   cs   = splat2(corr);
                sum1 = sum1 * corr + 1.f;
                #pragma unroll
                for (int j = 0; j < 8; j++) accp1[j] = mul2(accp1[j], cs);
                mx1 = s1; p1 = 1.f;
            } else {
                p1 = ex2f(s1 - mx1); sum1 += p1;
            }
            {
                u64 ps = splat2(p1);
                #pragma unroll
                for (int j = 0; j < 8; j++) ffma2(accp1[j], ps, vr[j]);
            }
        }
    }

    __syncthreads();   // phase-1 smem reads done; begin phase-2 overwrite

    {
        u64 inv0 = splat2(__fdividef(1.f, sum0));
        u64 inv1 = splat2(__fdividef(1.f, sum1));
        #pragma unroll
        for (int j = 0; j < 8; j++) {
            *(u64*)&outs[lane * 128 + h * 16 + 2 * j]        = mul2(accp0[j], inv0);
            *(u64*)&outs[(lane + 32) * 128 + h * 16 + 2 * j] = mul2(accp1[j], inv1);
        }
    }
    stage_wt(Wc, wcL, wcH, tid);
    if (tid < 128) sbc[tid] = bc[tid];
    __syncthreads();

    // mh = outs @ Wc^T + bc
    const int ty = tid >> 4, tx = tid & 15;
    const int r0 = ty * 4, c0 = tx * 8;
    u64 macc[4][4];
    #pragma unroll
    for (int i = 0; i < 4; i++)
        #pragma unroll
        for (int j = 0; j < 4; j++) macc[i][j] = 0ull;

    mm_body(outs, wcL, wcH, r0, tx, macc);

    u64 bb[4];
    #pragma unroll
    for (int j = 0; j < 4; j++) bb[j] = *(const u64*)&sbc[c0 + 2 * j];

    #pragma unroll
    for (int i = 0; i < 4; i++) {
        float* dst = g_MH + (b * N_ + n0 + r0 + i) * 128 + c0;
        ulonglong2 s0, s1;
        s0.x = add2(macc[i][0], bb[0]); s0.y = add2(macc[i][1], bb[1]);
        s1.x = add2(macc[i][2], bb[2]); s1.y = add2(macc[i][3], bb[3]);
        *(ulonglong2*)&dst[0] = s0;
        *(ulonglong2*)&dst[4] = s1;
    }
}

// =====================================================================
// Pointer logits: out = (10*tanh((MH @ enc^T)/sqrt(E)) + mask) * log2e
// (log2-scaled; softmax kernel finishes in-place). Grid: (N/64, B).
// =====================================================================
__global__ __launch_bounds__(256, 3) void pointer_gemm_kernel(
    const float* __restrict__ enc, const float* __restrict__ mask,
    float* __restrict__ out)
{
    extern __shared__ float sm[];
    float* smh  = sm;           // 64*128 = 8192
    float* enct = sm + 8192;    // 128*68 = 8704 (enc^T chunk, [e][m], stride 68)
    const int tid = threadIdx.x;
    const int b = blockIdx.y, n0 = blockIdx.x * 64;

    {
        const float4* Mh  = (const float4*)(g_MH + (b * N_ + n0) * 128);
        float4*       mh4 = (float4*)smh;
        #pragma unroll
        for (int i = 0; i < 8; i++) mh4[tid + 256 * i] = Mh[tid + 256 * i];
    }

    const int ty = tid >> 4, tx = tid & 15;
    const int r0 = ty * 4, m0l = tx * 4;
    const float U_SCALE = 2.f * LOG2E * 0.08838834764831845f; // 2*log2e/sqrt(128)

    for (int c = 0; c < 8; c++) {
        __syncthreads();
        {
            const float4* Eg = (const float4*)(enc + (b * N_ + c * 64) * 128);
            #pragma unroll
            for (int i = 0; i < 8; i++) {
                int    f  = tid + 256 * i;   // 2048 float4
                int    m  = f >> 5;
                int    e4 = (f & 31) << 2;
                float4 v  = Eg[f];
                enct[(e4 + 0) * 68 + m] = v.x;
                enct[(e4 + 1) * 68 + m] = v.y;
                enct[(e4 + 2) * 68 + m] = v.z;
                enct[(e4 + 3) * 68 + m] = v.w;
            }
        }
        __syncthreads();

        u64 acc[4][2];
        #pragma unroll
        for (int i = 0; i < 4; i++) { acc[i][0] = 0ull; acc[i][1] = 0ull; }

        #pragma unroll 4
        for (int e = 0; e < 128; e++) {
            ulonglong2 ev = *(const ulonglong2*)&enct[e * 68 + m0l];
            #pragma unroll
            for (int i = 0; i < 4; i++) {
                u64 as = splat2(smh[(r0 + i) * 128 + e]);
                ffma2(acc[i][0], as, ev.x);
                ffma2(acc[i][1], as, ev.y);
            }
        }

        const float* Mg = mask + (b * N_ + n0) * N_ + c * 64;
        #pragma unroll
        for (int i = 0; i < 4; i++) {
            float4 mv = *(const float4*)&Mg[(r0 + i) * N_ + m0l];
            float2 a0 = unpack2(acc[i][0]);
            float2 a1 = unpack2(acc[i][1]);
            float  sv[4] = {a0.x, a0.y, a1.x, a1.y};
            float  mk[4] = {mv.x, mv.y, mv.z, mv.w};
            float  res[4];
            #pragma unroll
            for (int j = 0; j < 4; j++) {
                float u  = sv[j] * U_SCALE;            // 2z*log2e
                float e2 = ex2f(u);                    // e^{2z}
                float t  = 1.f - __fdividef(2.f, e2 + 1.f);  // tanh z
                res[j] = fmaf(10.f * LOG2E, t, mk[j] * LOG2E);
            }
            *(float4*)&out[(b * N_ + n0 + r0 + i) * N_ + c * 64 + m0l] =
                make_float4(res[0], res[1], res[2], res[3]);
        }
    }
}

// =====================================================================
// In-place row softmax over 512-wide rows; input already log2-scaled.
// 256 threads = 8 warps, warp = row.
// =====================================================================
__global__ __launch_bounds__(256) void softmax512_kernel(float* __restrict__ out)
{
    const int row  = blockIdx.x * 8 + (threadIdx.x >> 5);
    const int lane = threadIdx.x & 31;
    float4* rp = (float4*)(out + row * 512);

    float4 v[4];
    #pragma unroll
    for (int k = 0; k < 4; k++) v[k] = rp[lane + 32 * k];

    float mx = -1e30f;
    #pragma unroll
    for (int k = 0; k < 4; k++) {
        mx = fmaxf(mx, fmaxf(fmaxf(v[k].x, v[k].y), fmaxf(v[k].z, v[k].w)));
    }
    #pragma unroll
    for (int off = 16; off >= 1; off >>= 1)
        mx = fmaxf(mx, __shfl_xor_sync(0xffffffffu, mx, off));

    float sum = 0.f;
    #pragma unroll
    for (int k = 0; k < 4; k++) {
        v[k].x = ex2f(v[k].x - mx); sum += v[k].x;
        v[k].y = ex2f(v[k].y - mx); sum += v[k].y;
        v[k].z = ex2f(v[k].z - mx); sum += v[k].z;
        v[k].w = ex2f(v[k].w - mx); sum += v[k].w;
    }
    #pragma unroll
    for (int off = 16; off >= 1; off >>= 1)
        sum += __shfl_xor_sync(0xffffffffu, sum, off);

    float inv = __fdividef(1.f, sum);
    #pragma unroll
    for (int k = 0; k < 4; k++) {
        v[k].x *= inv; v[k].y *= inv; v[k].z *= inv; v[k].w *= inv;
        rp[lane + 32 * k] = v[k];
    }
}

// =====================================================================
extern "C" void kernel_launch(void* const* d_in, const int* in_sizes, int n_in,
                              void* d_out, int out_size)
{
    const float* enc       = (const float*)d_in[0];
    const float* first_row = (const float*)d_in[1];
    const float* q0        = (const float*)d_in[2];
    const float* mask      = (const float*)d_in[3];
    const float* Wq0       = (const float*)d_in[4];
    const float* Wq1       = (const float*)d_in[5];
    const float* Wk        = (const float*)d_in[6];
    const float* Wv        = (const float*)d_in[7];
    const float* Wc        = (const float*)d_in[8];
    const float* bc        = (const float*)d_in[9];
    float*       out       = (float*)d_out;

    float *pK, *pV, *pQ;
    cudaGetSymbolAddress((void**)&pK, g_K);
    cudaGetSymbolAddress((void**)&pV, g_V);
    cudaGetSymbolAddress((void**)&pQ, g_Q);

    const int SMEM_G = 24576 * 4;  // 98304
    const int SMEM_A = 24704 * 4;  // 98816
    const int SMEM_P = 16896 * 4;  // 67584

    cudaFuncSetAttribute(gemm128_kernel<false>,
                         cudaFuncAttributeMaxDynamicSharedMemorySize, SMEM_G);
    cudaFuncSetAttribute(gemm128_kernel<true>,
                         cudaFuncAttributeMaxDynamicSharedMemorySize, SMEM_G);
    cudaFuncSetAttribute(attn_kernel,
                         cudaFuncAttributeMaxDynamicSharedMemorySize, SMEM_A);
    cudaFuncSetAttribute(pointer_gemm_kernel,
                         cudaFuncAttributeMaxDynamicSharedMemorySize, SMEM_P);

    gemm128_kernel<false><<<512, 256, SMEM_G>>>(first_row, Wq1, pQ);
    gemm128_kernel<true ><<<512, 256, SMEM_G>>>(q0,        Wq0, pQ);
    gemm128_kernel<false><<<512, 256, SMEM_G>>>(enc,       Wk,  pK);
    gemm128_kernel<false><<<512, 256, SMEM_G>>>(enc,       Wv,  pV);

    attn_kernel        <<<dim3(8, B_), 256, SMEM_A>>>(mask, Wc, bc);
    pointer_gemm_kernel<<<dim3(8, B_), 256, SMEM_P>>>(enc, mask, out);
    softmax512_kernel  <<<(B_ * N_) / 8, 256>>>(out);
}

// round 7
// speedup vs baseline: 1.6642x; 1.5501x over previous
#include <cuda_runtime.h>
#include <cuda_bf16.h>
#include <math.h>
#include <cstdint>

#define B_ 64
#define N_ 512
#define E_ 128
#define H_ 8
#define D_ 16

typedef unsigned long long u64;

// single unnamed dynamic-smem symbol for the whole TU
extern __shared__ char smraw[];

// ---------------- scratch (no allocations allowed) ----------------
__device__ float g_K [B_ * N_ * 128];
__device__ float g_V [B_ * N_ * 128];
__device__ float g_Q [B_ * N_ * 128];
__device__ float g_MH[B_ * N_ * 128];

#define LOG2E 1.4426950408889634f

// ---------------- small helpers ----------------
__device__ __forceinline__ uint32_t smem_u32(const void* p) {
    uint32_t a;
    asm("{ .reg .u64 t; cvta.to.shared.u64 t, %1; cvt.u32.u64 %0, t; }"
        : "=r"(a) : "l"(p));
    return a;
}
__device__ __forceinline__ float ex2f(float x) {
    float r; asm("ex2.approx.ftz.f32 %0, %1;" : "=f"(r) : "f"(x)); return r;
}
__device__ __forceinline__ void ldm4(uint32_t* r, uint32_t addr) {
    asm volatile("ldmatrix.sync.aligned.m8n8.x4.shared.b16 {%0,%1,%2,%3}, [%4];"
                 : "=r"(r[0]), "=r"(r[1]), "=r"(r[2]), "=r"(r[3]) : "r"(addr));
}
__device__ __forceinline__ void mma_bf16(float* d, const uint32_t* a,
                                         uint32_t b0, uint32_t b1) {
    asm volatile("mma.sync.aligned.m16n8k16.row.col.f32.bf16.bf16.f32 "
                 "{%0,%1,%2,%3}, {%4,%5,%6,%7}, {%8,%9}, {%0,%1,%2,%3};"
                 : "+f"(d[0]), "+f"(d[1]), "+f"(d[2]), "+f"(d[3])
                 : "r"(a[0]), "r"(a[1]), "r"(a[2]), "r"(a[3]), "r"(b0), "r"(b1));
}

// Byte offset of (row, k) in a 128x128-bf16 blocked SW128 tile (k mult of 4)
__device__ __forceinline__ uint32_t tile_off(int row, int k) {
    int ar = row >> 3, ir = row & 7, ac = k >> 6, ik = k & 63;
    uint32_t off = (uint32_t)((ac * 16 + ar) * 1024 + ir * 128 + ik * 2);
    return off ^ ((off >> 3) & 0x70);
}

__device__ __forceinline__ uint32_t pack_bf16(float a, float b) {
    __nv_bfloat16 ba = __float2bfloat16(a), bb = __float2bfloat16(b);
    return (uint32_t)*(unsigned short*)&ba | ((uint32_t)*(unsigned short*)&bb << 16);
}

// Stage a 128x128 fp32 row-major tile into swizzled bf16 hi/lo tiles (32KB each)
__device__ __forceinline__ void stage_tile(const float* __restrict__ src,
                                           char* dh, char* dl, int tid) {
    const float4* s4 = (const float4*)src;
    #pragma unroll
    for (int i = 0; i < 16; i++) {
        int f = tid + 256 * i;
        int row = f >> 5, k4 = (f & 31) << 2;
        float4 v = s4[f];
        float hx = __bfloat162float(__float2bfloat16(v.x));
        float hy = __bfloat162float(__float2bfloat16(v.y));
        float hz = __bfloat162float(__float2bfloat16(v.z));
        float hw = __bfloat162float(__float2bfloat16(v.w));
        uint2 hi, lo;
        hi.x = pack_bf16(v.x, v.y);
        hi.y = pack_bf16(v.z, v.w);
        lo.x = pack_bf16(v.x - hx, v.y - hy);
        lo.y = pack_bf16(v.z - hz, v.w - hw);
        uint32_t o = tile_off(row, k4);
        *(uint2*)(dh + o) = hi;
        *(uint2*)(dl + o) = lo;
    }
}

#define TILE_B 32768

// ---------------------------------------------------------------------
// Warp computes its 32x64 piece of A[128x128] @ W[128x128]^T with bf16x3
// split precision. Tiles (hi/lo) staged in smem. acc[2][8][4] fp32.
// wm in 0..3 (rows wm*32..+31), wn in 0..1 (cols wn*64..+63).
// ---------------------------------------------------------------------
__device__ __forceinline__ void warp_mm(uint32_t aH, uint32_t aL,
                                        uint32_t bH, uint32_t bL,
                                        int wm, int wn, int lane,
                                        float (*acc)[8][4])
{
    const int ir = lane & 7, j = lane >> 3;
    const int jmA = (j & 1) * 8;   // A matrices: (m0,k0),(m0+8,k0),(m0,k0+8),(m0+8,k0+8)
    const int jkA = (j >> 1) * 8;
    const int jnB = (j >> 1) * 8;  // B matrices: (n0,k0),(n0,k0+8),(n0+8,k0),(n0+8,k0+8)
    const int jkB = (j & 1) * 8;
    const uint32_t swz = (uint32_t)(ir * 128) ;
    const uint32_t xr  = (uint32_t)(ir << 4);

    #pragma unroll
    for (int ks = 0; ks < 8; ks++) {
        const int k0 = ks * 16;
        uint32_t ah[2][4], al[2][4];
        #pragma unroll
        for (int ma = 0; ma < 2; ma++) {
            int row = wm * 32 + ma * 16 + jmA + ir;
            int k   = k0 + jkA;
            uint32_t off = (uint32_t)(((k >> 6) * 16 + (row >> 3)) * 1024)
                         + swz + ((uint32_t)((k & 63) * 2) ^ xr);
            ldm4(ah[ma], aH + off);
            ldm4(al[ma], aL + off);
        }
        #pragma unroll
        for (int np = 0; np < 4; np++) {
            int n = wn * 64 + np * 16 + jnB + ir;
            int k = k0 + jkB;
            uint32_t off = (uint32_t)(((k >> 6) * 16 + (n >> 3)) * 1024)
                         + swz + ((uint32_t)((k & 63) * 2) ^ xr);
            uint32_t bh[4], bl[4];
            ldm4(bh, bH + off);
            ldm4(bl, bL + off);
            #pragma unroll
            for (int ma = 0; ma < 2; ma++) {
                mma_bf16(acc[ma][2 * np],     ah[ma], bh[0], bh[1]);
                mma_bf16(acc[ma][2 * np],     ah[ma], bl[0], bl[1]);
                mma_bf16(acc[ma][2 * np],     al[ma], bh[0], bh[1]);
                mma_bf16(acc[ma][2 * np + 1], ah[ma], bh[2], bh[3]);
                mma_bf16(acc[ma][2 * np + 1], ah[ma], bl[2], bl[3]);
                mma_bf16(acc[ma][2 * np + 1], al[ma], bh[2], bh[3]);
            }
        }
    }
}

__device__ __forceinline__ void zero_acc(float (*acc)[8][4]) {
    #pragma unroll
    for (int i = 0; i < 2; i++)
        #pragma unroll
        for (int j = 0; j < 8; j++)
            #pragma unroll
            for (int q = 0; q < 4; q++) acc[i][j][q] = 0.f;
}

// =====================================================================
// Generic: C[row0:+128, 0:128] = A[row0:+128, :] @ W^T    (grid 256)
// =====================================================================
__global__ __launch_bounds__(256, 1)
void gemm_tc_kernel(const float* __restrict__ A, const float* __restrict__ W,
                    float* __restrict__ C)
{
    char* aHc = smraw;
    char* aLc = aHc + TILE_B;
    char* bHc = aLc + TILE_B;
    char* bLc = bHc + TILE_B;
    const int tid = threadIdx.x, lane = tid & 31, wid = tid >> 5;
    const int wm = wid & 3, wn = wid >> 2;
    const int row0 = blockIdx.x * 128;

    stage_tile(A + row0 * 128, aHc, aLc, tid);
    stage_tile(W, bHc, bLc, tid);
    __syncthreads();

    float acc[2][8][4];
    zero_acc(acc);
    warp_mm(smem_u32(aHc), smem_u32(aLc), smem_u32(bHc), smem_u32(bLc),
            wm, wn, lane, acc);

    #pragma unroll
    for (int ma = 0; ma < 2; ma++) {
        int r = row0 + wm * 32 + ma * 16 + (lane >> 2);
        #pragma unroll
        for (int na = 0; na < 8; na++) {
            int c = wn * 64 + na * 8 + (lane & 3) * 2;
            *(float2*)&C[r * 128 + c]       = make_float2(acc[ma][na][0], acc[ma][na][1]);
            *(float2*)&C[(r + 8) * 128 + c] = make_float2(acc[ma][na][2], acc[ma][na][3]);
        }
    }
}

// =====================================================================
// Q projection: g_Q = first_row@Wq1^T + q0@Wq0^T  (two accumulate passes)
// =====================================================================
__global__ __launch_bounds__(256, 1)
void qproj_kernel(const float* __restrict__ fr, const float* __restrict__ q0,
                  const float* __restrict__ Wq1, const float* __restrict__ Wq0,
                  float* __restrict__ C)
{
    char* aHc = smraw;
    char* aLc = aHc + TILE_B;
    char* bHc = aLc + TILE_B;
    char* bLc = bHc + TILE_B;
    const int tid = threadIdx.x, lane = tid & 31, wid = tid >> 5;
    const int wm = wid & 3, wn = wid >> 2;
    const int row0 = blockIdx.x * 128;

    float acc[2][8][4];
    zero_acc(acc);

    stage_tile(fr + row0 * 128, aHc, aLc, tid);
    stage_tile(Wq1, bHc, bLc, tid);
    __syncthreads();
    warp_mm(smem_u32(aHc), smem_u32(aLc), smem_u32(bHc), smem_u32(bLc),
            wm, wn, lane, acc);
    __syncthreads();

    stage_tile(q0 + row0 * 128, aHc, aLc, tid);
    stage_tile(Wq0, bHc, bLc, tid);
    __syncthreads();
    warp_mm(smem_u32(aHc), smem_u32(aLc), smem_u32(bHc), smem_u32(bLc),
            wm, wn, lane, acc);

    #pragma unroll
    for (int ma = 0; ma < 2; ma++) {
        int r = row0 + wm * 32 + ma * 16 + (lane >> 2);
        #pragma unroll
        for (int na = 0; na < 8; na++) {
            int c = wn * 64 + na * 8 + (lane & 3) * 2;
            *(float2*)&C[r * 128 + c]       = make_float2(acc[ma][na][0], acc[ma][na][1]);
            *(float2*)&C[(r + 8) * 128 + c] = make_float2(acc[ma][na][2], acc[ma][na][3]);
        }
    }
}

// =====================================================================
// Pointer logits: out = (10*tanh((MH@enc^T)/sqrt(E)) + mask) * log2e
// grid (4, 64): 128-row MH tile x batch; 4 chunks of 128 enc rows each.
// =====================================================================
__global__ __launch_bounds__(256, 1)
void pointer_tc_kernel(const float* __restrict__ enc, const float* __restrict__ mask,
                       float* __restrict__ out)
{
    char* aHc = smraw;
    char* aLc = aHc + TILE_B;
    char* bHc = aLc + TILE_B;
    char* bLc = bHc + TILE_B;
    const int tid = threadIdx.x, lane = tid & 31, wid = tid >> 5;
    const int wm = wid & 3, wn = wid >> 2;
    const int b = blockIdx.y, n0 = blockIdx.x * 128;
    const float U_SCALE = 2.f * LOG2E * 0.08838834764831845f; // 2*log2e/sqrt(128)

    stage_tile(g_MH + (b * N_ + n0) * 128, aHc, aLc, tid);

    for (int c = 0; c < 4; c++) {
        if (c) __syncthreads();    // prior ldmatrix reads done before restage
        stage_tile(enc + (b * N_ + c * 128) * 128, bHc, bLc, tid);
        __syncthreads();

        float acc[2][8][4];
        zero_acc(acc);
        warp_mm(smem_u32(aHc), smem_u32(aLc), smem_u32(bHc), smem_u32(bLc),
                wm, wn, lane, acc);

        // epilogue: tanh-clip + mask, write log2-scaled logits
        #pragma unroll
        for (int ma = 0; ma < 2; ma++) {
            int r = n0 + wm * 32 + ma * 16 + (lane >> 2);
            #pragma unroll
            for (int na = 0; na < 8; na++) {
                int col = c * 128 + wn * 64 + na * 8 + (lane & 3) * 2;
                #pragma unroll
                for (int half = 0; half < 2; half++) {
                    int rr = r + half * 8;
                    const float2 mv = *(const float2*)&mask[(b * N_ + rr) * N_ + col];
                    float res[2];
                    #pragma unroll
                    for (int q = 0; q < 2; q++) {
                        float s  = acc[ma][na][half * 2 + q];
                        float u  = s * U_SCALE;
                        float e2 = ex2f(u);
                        float t  = 1.f - __fdividef(2.f, e2 + 1.f);
                        float mk = (q == 0) ? mv.x : mv.y;
                        res[q] = fmaf(10.f * LOG2E, t, mk * LOG2E);
                    }
                    *(float2*)&out[(b * N_ + rr) * N_ + col] = make_float2(res[0], res[1]);
                }
            }
        }
    }
}

// ---------------- f32x2 helpers (attention scalar path) ----------------
__device__ __forceinline__ void ffma2(u64& d, u64 a, u64 b) {
    asm("fma.rn.f32x2 %0, %1, %2, %0;" : "+l"(d) : "l"(a), "l"(b));
}
__device__ __forceinline__ u64 mul2(u64 a, u64 b) {
    u64 r; asm("mul.rn.f32x2 %0, %1, %2;" : "=l"(r) : "l"(a), "l"(b)); return r;
}
__device__ __forceinline__ u64 add2(u64 a, u64 b) {
    u64 r; asm("add.rn.f32x2 %0, %1, %2;" : "=l"(r) : "l"(a), "l"(b)); return r;
}
__device__ __forceinline__ u64 splat2(float x) {
    u64 r; asm("mov.b64 %0, {%1, %1};" : "=l"(r) : "f"(x)); return r;
}
__device__ __forceinline__ float2 unpack2(u64 v) {
    float2 f; asm("mov.b64 {%0, %1}, %2;" : "=f"(f.x), "=f"(f.y) : "l"(v)); return f;
}

__device__ __forceinline__ void stage_wt(const float* __restrict__ W,
                                         float* swL, float* swH, int tid)
{
    const float4* Wg = (const float4*)W;
    #pragma unroll
    for (int i = 0; i < 16; i++) {
        int    f  = tid + 256 * i;
        int    o  = f >> 5;
        int    e4 = (f & 31) << 2;
        float4 w  = Wg[f];
        int    g  = o >> 3, j = o & 7;
        float* base = (j < 4) ? swL : swH;
        int    jj   = g * 4 + (j & 3);
        base[(e4 + 0) * 64 + jj] = w.x;
        base[(e4 + 1) * 64 + jj] = w.y;
        base[(e4 + 2) * 64 + jj] = w.z;
        base[(e4 + 3) * 64 + jj] = w.w;
    }
}

__device__ __forceinline__ void mm_body(const float* sa, const float* swL,
                                        const float* swH, int r0, int tx,
                                        u64 acc[4][4])
{
    #pragma unroll 2
    for (int e4 = 0; e4 < 128; e4 += 4) {
        float4 av[4];
        #pragma unroll
        for (int i = 0; i < 4; i++) av[i] = *(const float4*)&sa[(r0 + i) * 128 + e4];
        ulonglong2 wl[4], wh[4];
        #pragma unroll
        for (int e = 0; e < 4; e++) {
            wl[e] = *(const ulonglong2*)&swL[(e4 + e) * 64 + tx * 4];
            wh[e] = *(const ulonglong2*)&swH[(e4 + e) * 64 + tx * 4];
        }
        #pragma unroll
        for (int e = 0; e < 4; e++) {
            #pragma unroll
            for (int i = 0; i < 4; i++) {
                u64 as = splat2(((const float*)&av[i])[e]);
                ffma2(acc[i][0], as, wl[e].x);
                ffma2(acc[i][1], as, wl[e].y);
                ffma2(acc[i][2], as, wh[e].x);
                ffma2(acc[i][3], as, wh[e].y);
            }
        }
    }
}

// =====================================================================
// Attention (online softmax, log2 domain) + output projection -> g_MH
// =====================================================================
__global__ __launch_bounds__(256, 2) void attn_kernel(
    const float* __restrict__ mask, const float* __restrict__ Wc,
    const float* __restrict__ bc)
{
    float* sm = (float*)smraw;
    float* ks = sm;
    float* vs = sm + 8192;
    float* ms = sm + 16384;
    float* wcL  = sm;
    float* wcH  = sm + 8192;
    float* outs = sm + 16384;
    float* sbc  = sm + 24576;

    const int tid  = threadIdx.x;
    const int lane = tid & 31, h = tid >> 5;
    const int b = blockIdx.y, n0 = blockIdx.x * 64;

    u64 q0p[8], q1p[8];
    {
        const u64* Qg0 = (const u64*)(g_Q + (b * N_ + n0 + lane) * 128 + h * 16);
        const u64* Qg1 = (const u64*)(g_Q + (b * N_ + n0 + lane + 32) * 128 + h * 16);
        const u64 cs = splat2(0.25f * LOG2E);
        #pragma unroll
        for (int j = 0; j < 8; j++) {
            q0p[j] = mul2(Qg0[j], cs);
            q1p[j] = mul2(Qg1[j], cs);
        }
    }

    u64 accp0[8], accp1[8];
    #pragma unroll
    for (int j = 0; j < 8; j++) { accp0[j] = 0ull; accp1[j] = 0ull; }
    float mx0 = -1e30f, mx1 = -1e30f, sum0 = 0.f, sum1 = 0.f;

    for (int c = 0; c < 8; c++) {
        const int m0 = c * 64;
        __syncthreads();
        {
            const float4* Kg = (const float4*)(g_K + (b * N_ + m0) * 128);
            const float4* Vg = (const float4*)(g_V + (b * N_ + m0) * 128);
            float4* k4 = (float4*)ks;
            float4* v4 = (float4*)vs;
            #pragma unroll
            for (int i = 0; i < 8; i++) {
                k4[tid + 256 * i] = Kg[tid + 256 * i];
                v4[tid + 256 * i] = Vg[tid + 256 * i];
            }
            const float* Mg = mask + (b * N_ + n0) * N_ + m0;
            #pragma unroll
            for (int i = 0; i < 16; i++) {
                int f = tid + 256 * i;
                int r = f >> 6, m = f & 63;
                ms[r * 65 + m] = Mg[r * N_ + m] * LOG2E;
            }
        }
        __syncthreads();

        for (int m = 0; m < 64; m++) {
            const ulonglong2* kp = (const ulonglong2*)(ks + m * 128 + h * 16);
            u64 kr[8];
            #pragma unroll
            for (int j = 0; j < 4; j++) {
                ulonglong2 t = kp[j]; kr[2 * j] = t.x; kr[2 * j + 1] = t.y;
            }
            u64 d0 = 0ull, d1 = 0ull;
            #pragma unroll
            for (int j = 0; j < 8; j++) {
                ffma2(d0, q0p[j], kr[j]);
                ffma2(d1, q1p[j], kr[j]);
            }
            float2 f0 = unpack2(d0), f1 = unpack2(d1);
            float s0 = f0.x + f0.y + ms[lane * 65 + m];
            float s1 = f1.x + f1.y + ms[(lane + 32) * 65 + m];

            const ulonglong2* vp = (const ulonglong2*)(vs + m * 128 + h * 16);
            u64 vr[8];
            #pragma unroll
            for (int j = 0; j < 4; j++) {
                ulonglong2 t = vp[j]; vr[2 * j] = t.x; vr[2 * j + 1] = t.y;
            }

            float p0, p1;
            if (s0 > mx0) {
                float corr = ex2f(mx0 - s0);
                u64   cs   = splat2(corr);
                sum0 = sum0 * corr + 1.f;
                #pragma unroll
                for (int j = 0; j < 8; j++) accp0[j] = mul2(accp0[j], cs);
                mx0 = s0; p0 = 1.f;
            } else {
                p0 = ex2f(s0 - mx0); sum0 += p0;
            }
            {
                u64 ps = splat2(p0);
                #pragma unroll
                for (int j = 0; j < 8; j++) ffma2(accp0[j], ps, vr[j]);
            }

            if (s1 > mx1) {
                float corr = ex2f(mx1 - s1);
                u64   cs   = splat2(corr);
                sum1 = sum1 * corr + 1.f;
                #pragma unroll
                for (int j = 0; j < 8; j++) accp1[j] = mul2(accp1[j], cs);
                mx1 = s1; p1 = 1.f;
            } else {
                p1 = ex2f(s1 - mx1); sum1 += p1;
            }
            {
                u64 ps = splat2(p1);
                #pragma unroll
                for (int j = 0; j < 8; j++) ffma2(accp1[j], ps, vr[j]);
            }
        }
    }

    __syncthreads();

    {
        u64 inv0 = splat2(__fdividef(1.f, sum0));
        u64 inv1 = splat2(__fdividef(1.f, sum1));
        #pragma unroll
        for (int j = 0; j < 8; j++) {
            *(u64*)&outs[lane * 128 + h * 16 + 2 * j]        = mul2(accp0[j], inv0);
            *(u64*)&outs[(lane + 32) * 128 + h * 16 + 2 * j] = mul2(accp1[j], inv1);
        }
    }
    stage_wt(Wc, wcL, wcH, tid);
    if (tid < 128) sbc[tid] = bc[tid];
    __syncthreads();

    const int ty = tid >> 4, tx = tid & 15;
    const int r0 = ty * 4, c0 = tx * 8;
    u64 macc[4][4];
    #pragma unroll
    for (int i = 0; i < 4; i++)
        #pragma unroll
        for (int j = 0; j < 4; j++) macc[i][j] = 0ull;

    mm_body(outs, wcL, wcH, r0, tx, macc);

    u64 bb[4];
    #pragma unroll
    for (int j = 0; j < 4; j++) bb[j] = *(const u64*)&sbc[c0 + 2 * j];

    #pragma unroll
    for (int i = 0; i < 4; i++) {
        float* dst = g_MH + (b * N_ + n0 + r0 + i) * 128 + c0;
        ulonglong2 s0, s1;
        s0.x = add2(macc[i][0], bb[0]); s0.y = add2(macc[i][1], bb[1]);
        s1.x = add2(macc[i][2], bb[2]); s1.y = add2(macc[i][3], bb[3]);
        *(ulonglong2*)&dst[0] = s0;
        *(ulonglong2*)&dst[4] = s1;
    }
}

// =====================================================================
// In-place row softmax over 512-wide rows; input is log2-scaled.
// =====================================================================
__global__ __launch_bounds__(256) void softmax512_kernel(float* __restrict__ out)
{
    const int row  = blockIdx.x * 8 + (threadIdx.x >> 5);
    const int lane = threadIdx.x & 31;
    float4* rp = (float4*)(out + row * 512);

    float4 v[4];
    #pragma unroll
    for (int k = 0; k < 4; k++) v[k] = rp[lane + 32 * k];

    float mx = -1e30f;
    #pragma unroll
    for (int k = 0; k < 4; k++)
        mx = fmaxf(mx, fmaxf(fmaxf(v[k].x, v[k].y), fmaxf(v[k].z, v[k].w)));
    #pragma unroll
    for (int off = 16; off >= 1; off >>= 1)
        mx = fmaxf(mx, __shfl_xor_sync(0xffffffffu, mx, off));

    float sum = 0.f;
    #pragma unroll
    for (int k = 0; k < 4; k++) {
        v[k].x = ex2f(v[k].x - mx); sum += v[k].x;
        v[k].y = ex2f(v[k].y - mx); sum += v[k].y;
        v[k].z = ex2f(v[k].z - mx); sum += v[k].z;
        v[k].w = ex2f(v[k].w - mx); sum += v[k].w;
    }
    #pragma unroll
    for (int off = 16; off >= 1; off >>= 1)
        sum += __shfl_xor_sync(0xffffffffu, sum, off);

    float inv = __fdividef(1.f, sum);
    #pragma unroll
    for (int k = 0; k < 4; k++) {
        v[k].x *= inv; v[k].y *= inv; v[k].z *= inv; v[k].w *= inv;
        rp[lane + 32 * k] = v[k];
    }
}

// =====================================================================
extern "C" void kernel_launch(void* const* d_in, const int* in_sizes, int n_in,
                              void* d_out, int out_size)
{
    const float* enc       = (const float*)d_in[0];
    const float* first_row = (const float*)d_in[1];
    const float* q0        = (const float*)d_in[2];
    const float* mask      = (const float*)d_in[3];
    const float* Wq0       = (const float*)d_in[4];
    const float* Wq1       = (const float*)d_in[5];
    const float* Wk        = (const float*)d_in[6];
    const float* Wv        = (const float*)d_in[7];
    const float* Wc        = (const float*)d_in[8];
    const float* bc        = (const float*)d_in[9];
    float*       out       = (float*)d_out;

    float *pK, *pV, *pQ;
    cudaGetSymbolAddress((void**)&pK, g_K);
    cudaGetSymbolAddress((void**)&pV, g_V);
    cudaGetSymbolAddress((void**)&pQ, g_Q);

    const int SMEM_T = 4 * TILE_B;   // 131072
    const int SMEM_A = 24704 * 4;    // 98816

    cudaFuncSetAttribute(gemm_tc_kernel,
                         cudaFuncAttributeMaxDynamicSharedMemorySize, SMEM_T);
    cudaFuncSetAttribute(qproj_kernel,
                         cudaFuncAttributeMaxDynamicSharedMemorySize, SMEM_T);
    cudaFuncSetAttribute(pointer_tc_kernel,
                         cudaFuncAttributeMaxDynamicSharedMemorySize, SMEM_T);
    cudaFuncSetAttribute(attn_kernel,
                         cudaFuncAttributeMaxDynamicSharedMemorySize, SMEM_A);

    gemm_tc_kernel<<<256, 256, SMEM_T>>>(enc, Wk, pK);
    gemm_tc_kernel<<<256, 256, SMEM_T>>>(enc, Wv, pV);
    qproj_kernel  <<<256, 256, SMEM_T>>>(first_row, q0, Wq1, Wq0, pQ);

    attn_kernel<<<dim3(8, B_), 256, SMEM_A>>>(mask, Wc, bc);

    pointer_tc_kernel<<<dim3(4, B_), 256, SMEM_T>>>(enc, mask, out);
    softmax512_kernel<<<(B_ * N_) / 8, 256>>>(out);
}

// round 8
// speedup vs baseline: 2.2253x; 1.3372x over previous
#include <cuda_runtime.h>
#include <cuda_bf16.h>
#include <math.h>
#include <cstdint>

#define B_ 64
#define N_ 512
#define E_ 128
#define H_ 8
#define D_ 16

typedef unsigned long long u64;

// single unnamed dynamic-smem symbol for the whole TU
extern __shared__ char smraw[];

// ---------------- scratch (no allocations allowed) ----------------
__device__ float g_K [B_ * N_ * 128];
__device__ float g_V [B_ * N_ * 128];
__device__ float g_Q [B_ * N_ * 128];
__device__ float g_MH[B_ * N_ * 128];

#define LOG2E 1.4426950408889634f

// ---------------- small helpers ----------------
__device__ __forceinline__ uint32_t smem_u32(const void* p) {
    uint32_t a;
    asm("{ .reg .u64 t; cvta.to.shared.u64 t, %1; cvt.u32.u64 %0, t; }"
        : "=r"(a) : "l"(p));
    return a;
}
__device__ __forceinline__ float ex2f(float x) {
    float r; asm("ex2.approx.ftz.f32 %0, %1;" : "=f"(r) : "f"(x)); return r;
}
__device__ __forceinline__ void ldm4(uint32_t* r, uint32_t addr) {
    asm volatile("ldmatrix.sync.aligned.m8n8.x4.shared.b16 {%0,%1,%2,%3}, [%4];"
                 : "=r"(r[0]), "=r"(r[1]), "=r"(r[2]), "=r"(r[3]) : "r"(addr));
}
__device__ __forceinline__ void ldm4t(uint32_t* r, uint32_t addr) {
    asm volatile("ldmatrix.sync.aligned.m8n8.x4.trans.shared.b16 {%0,%1,%2,%3}, [%4];"
                 : "=r"(r[0]), "=r"(r[1]), "=r"(r[2]), "=r"(r[3]) : "r"(addr));
}
__device__ __forceinline__ void mma_bf16(float* d, const uint32_t* a,
                                         uint32_t b0, uint32_t b1) {
    asm volatile("mma.sync.aligned.m16n8k16.row.col.f32.bf16.bf16.f32 "
                 "{%0,%1,%2,%3}, {%4,%5,%6,%7}, {%8,%9}, {%0,%1,%2,%3};"
                 : "+f"(d[0]), "+f"(d[1]), "+f"(d[2]), "+f"(d[3])
                 : "r"(a[0]), "r"(a[1]), "r"(a[2]), "r"(a[3]), "r"(b0), "r"(b1));
}

// Byte offset of (row, k) in a 128x128-bf16 blocked SW128 tile
__device__ __forceinline__ uint32_t tile_off(int row, int k) {
    uint32_t off = (uint32_t)((((k >> 6) * 16 + (row >> 3)) * 1024)
                              + (row & 7) * 128 + (k & 63) * 2);
    return off ^ ((off >> 3) & 0x70);
}
// Byte offset of (row, k) in a 64x128-bf16 blocked SW128 tile
__device__ __forceinline__ uint32_t off64(int row, int k) {
    uint32_t off = (uint32_t)((((k >> 6) * 8 + (row >> 3)) * 1024)
                              + (row & 7) * 128 + (k & 63) * 2);
    return off ^ ((off >> 3) & 0x70);
}

__device__ __forceinline__ uint32_t pack_bf16(float a, float b) {
    __nv_bfloat16 ba = __float2bfloat16(a), bb = __float2bfloat16(b);
    return (uint32_t)*(unsigned short*)&ba | ((uint32_t)*(unsigned short*)&bb << 16);
}
__device__ __forceinline__ void split2(float x, float y, uint32_t& hi, uint32_t& lo) {
    __nv_bfloat16 bx = __float2bfloat16(x), by = __float2bfloat16(y);
    hi = (uint32_t)*(unsigned short*)&bx | ((uint32_t)*(unsigned short*)&by << 16);
    lo = pack_bf16(x - __bfloat162float(bx), y - __bfloat162float(by));
}

// Stage a 128x128 fp32 row-major tile into swizzled bf16 hi/lo tiles (32KB each)
__device__ __forceinline__ void stage_tile(const float* __restrict__ src,
                                           char* dh, char* dl, int tid) {
    const float4* s4 = (const float4*)src;
    #pragma unroll
    for (int i = 0; i < 16; i++) {
        int f = tid + 256 * i;
        int row = f >> 5, k4 = (f & 31) << 2;
        float4 v = s4[f];
        uint2 hi, lo;
        split2(v.x, v.y, hi.x, lo.x);
        split2(v.z, v.w, hi.y, lo.y);
        uint32_t o = tile_off(row, k4);
        *(uint2*)(dh + o) = hi;
        *(uint2*)(dl + o) = lo;
    }
}
// Stage a 64x128 fp32 tile into swizzled bf16 hi/lo (16KB each), scaled
__device__ __forceinline__ void stage64(const float* __restrict__ src,
                                        char* dh, char* dl, int tid, float scale) {
    const float4* s4 = (const float4*)src;
    #pragma unroll
    for (int i = 0; i < 8; i++) {
        int f = tid + 256 * i;
        int row = f >> 5, k4 = (f & 31) << 2;
        float4 v = s4[f];
        v.x *= scale; v.y *= scale; v.z *= scale; v.w *= scale;
        uint2 hi, lo;
        split2(v.x, v.y, hi.x, lo.x);
        split2(v.z, v.w, hi.y, lo.y);
        uint32_t o = off64(row, k4);
        *(uint2*)(dh + o) = hi;
        *(uint2*)(dl + o) = lo;
    }
}

#define TILE_B 32768

// ---------------------------------------------------------------------
// Warp computes its 32x64 piece of A[128x128] @ W[128x128]^T (bf16x3).
// ---------------------------------------------------------------------
__device__ __forceinline__ void warp_mm(uint32_t aH, uint32_t aL,
                                        uint32_t bH, uint32_t bL,
                                        int wm, int wn, int lane,
                                        float (*acc)[8][4])
{
    const int ir = lane & 7, j = lane >> 3;
    const int jmA = (j & 1) * 8, jkA = (j >> 1) * 8;
    const int jnB = (j >> 1) * 8, jkB = (j & 1) * 8;

    #pragma unroll
    for (int ks = 0; ks < 8; ks++) {
        const int k0 = ks * 16;
        uint32_t ah[2][4], al[2][4];
        #pragma unroll
        for (int ma = 0; ma < 2; ma++) {
            uint32_t off = tile_off(wm * 32 + ma * 16 + jmA + ir, k0 + jkA);
            ldm4(ah[ma], aH + off);
            ldm4(al[ma], aL + off);
        }
        #pragma unroll
        for (int np = 0; np < 4; np++) {
            uint32_t off = tile_off(wn * 64 + np * 16 + jnB + ir, k0 + jkB);
            uint32_t bh[4], bl[4];
            ldm4(bh, bH + off);
            ldm4(bl, bL + off);
            #pragma unroll
            for (int ma = 0; ma < 2; ma++) {
                mma_bf16(acc[ma][2 * np],     ah[ma], bh[0], bh[1]);
                mma_bf16(acc[ma][2 * np],     ah[ma], bl[0], bl[1]);
                mma_bf16(acc[ma][2 * np],     al[ma], bh[0], bh[1]);
                mma_bf16(acc[ma][2 * np + 1], ah[ma], bh[2], bh[3]);
                mma_bf16(acc[ma][2 * np + 1], ah[ma], bl[2], bl[3]);
                mma_bf16(acc[ma][2 * np + 1], al[ma], bh[2], bh[3]);
            }
        }
    }
}

__device__ __forceinline__ void zero_acc(float (*acc)[8][4]) {
    #pragma unroll
    for (int i = 0; i < 2; i++)
        #pragma unroll
        for (int j = 0; j < 8; j++)
            #pragma unroll
            for (int q = 0; q < 4; q++) acc[i][j][q] = 0.f;
}

// =====================================================================
// C[row0:+128, 0:128] = A[row0:+128, :] @ W^T    (grid 256)
// =====================================================================
__global__ __launch_bounds__(256, 1)
void gemm_tc_kernel(const float* __restrict__ A, const float* __restrict__ W,
                    float* __restrict__ C)
{
    char* aHc = smraw;
    char* aLc = aHc + TILE_B;
    char* bHc = aLc + TILE_B;
    char* bLc = bHc + TILE_B;
    const int tid = threadIdx.x, lane = tid & 31, wid = tid >> 5;
    const int wm = wid & 3, wn = wid >> 2;
    const int row0 = blockIdx.x * 128;

    stage_tile(A + row0 * 128, aHc, aLc, tid);
    stage_tile(W, bHc, bLc, tid);
    __syncthreads();

    float acc[2][8][4];
    zero_acc(acc);
    warp_mm(smem_u32(aHc), smem_u32(aLc), smem_u32(bHc), smem_u32(bLc),
            wm, wn, lane, acc);

    #pragma unroll
    for (int ma = 0; ma < 2; ma++) {
        int r = row0 + wm * 32 + ma * 16 + (lane >> 2);
        #pragma unroll
        for (int na = 0; na < 8; na++) {
            int c = wn * 64 + na * 8 + (lane & 3) * 2;
            *(float2*)&C[r * 128 + c]       = make_float2(acc[ma][na][0], acc[ma][na][1]);
            *(float2*)&C[(r + 8) * 128 + c] = make_float2(acc[ma][na][2], acc[ma][na][3]);
        }
    }
}

// =====================================================================
// Q projection: g_Q = first_row@Wq1^T + q0@Wq0^T
// =====================================================================
__global__ __launch_bounds__(256, 1)
void qproj_kernel(const float* __restrict__ fr, const float* __restrict__ q0,
                  const float* __restrict__ Wq1, const float* __restrict__ Wq0,
                  float* __restrict__ C)
{
    char* aHc = smraw;
    char* aLc = aHc + TILE_B;
    char* bHc = aLc + TILE_B;
    char* bLc = bHc + TILE_B;
    const int tid = threadIdx.x, lane = tid & 31, wid = tid >> 5;
    const int wm = wid & 3, wn = wid >> 2;
    const int row0 = blockIdx.x * 128;

    float acc[2][8][4];
    zero_acc(acc);

    stage_tile(fr + row0 * 128, aHc, aLc, tid);
    stage_tile(Wq1, bHc, bLc, tid);
    __syncthreads();
    warp_mm(smem_u32(aHc), smem_u32(aLc), smem_u32(bHc), smem_u32(bLc),
            wm, wn, lane, acc);
    __syncthreads();

    stage_tile(q0 + row0 * 128, aHc, aLc, tid);
    stage_tile(Wq0, bHc, bLc, tid);
    __syncthreads();
    warp_mm(smem_u32(aHc), smem_u32(aLc), smem_u32(bHc), smem_u32(bLc),
            wm, wn, lane, acc);

    #pragma unroll
    for (int ma = 0; ma < 2; ma++) {
        int r = row0 + wm * 32 + ma * 16 + (lane >> 2);
        #pragma unroll
        for (int na = 0; na < 8; na++) {
            int c = wn * 64 + na * 8 + (lane & 3) * 2;
            *(float2*)&C[r * 128 + c]       = make_float2(acc[ma][na][0], acc[ma][na][1]);
            *(float2*)&C[(r + 8) * 128 + c] = make_float2(acc[ma][na][2], acc[ma][na][3]);
        }
    }
}

// =====================================================================
// Flash attention (bf16x3 HMMA) + output projection.  grid (8, 64).
// 8 warps, warp = head; 64 q-rows per block; 8 chunks x 64 keys.
// =====================================================================
#define SA_QH   0
#define SA_QL   16384
#define SA_KH   32768
#define SA_KL   49152
#define SA_VH   65536
#define SA_VL   81920
#define SA_WCH  98304
#define SA_WCL  131072
#define SA_MS   163840    // 64*68 floats
#define SA_BC   181248    // 128 floats
#define SA_OUTS 0         // overlay (epilogue): 64*128 fp32
#define SA_OH   32768     // overlay (epilogue)
#define SA_OL   49152
#define SMEM_ATT (181248 + 512)

__global__ __launch_bounds__(256, 1)
void attn_kernel(const float* __restrict__ mask, const float* __restrict__ Wc,
                 const float* __restrict__ bc)
{
    const int tid = threadIdx.x, lane = tid & 31, h = tid >> 5;
    const int b = blockIdx.y, n0 = blockIdx.x * 64;
    const int ir = lane & 7, j = lane >> 3;
    const int jmA = (j & 1) * 8, jkA = (j >> 1) * 8;
    const int jnB = (j >> 1) * 8, jkB = (j & 1) * 8;
    float* ms  = (float*)(smraw + SA_MS);
    float* sbc = (float*)(smraw + SA_BC);

    stage64(g_Q + ((size_t)b * N_ + n0) * 128, smraw + SA_QH, smraw + SA_QL,
            tid, 0.25f * LOG2E);
    stage_tile(Wc, smraw + SA_WCH, smraw + SA_WCL, tid);
    if (tid < 128) sbc[tid] = bc[tid];
    __syncthreads();

    // Q fragments (A operand), hi/lo
    uint32_t qh[4][4], ql[4][4];
    {
        uint32_t qb = smem_u32(smraw + SA_QH), qlb = smem_u32(smraw + SA_QL);
        #pragma unroll
        for (int ma = 0; ma < 4; ma++) {
            uint32_t off = off64(ma * 16 + jmA + ir, h * 16 + jkA);
            ldm4(qh[ma], qb + off);
            ldm4(ql[ma], qlb + off);
        }
    }

    float O[4][2][4];
    #pragma unroll
    for (int a = 0; a < 4; a++)
        #pragma unroll
        for (int d = 0; d < 2; d++)
            #pragma unroll
            for (int q = 0; q < 4; q++) O[a][d][q] = 0.f;
    float mx[8], sml[8];
    #pragma unroll
    for (int s = 0; s < 8; s++) { mx[s] = -1e30f; sml[s] = 0.f; }

    const uint32_t kHb = smem_u32(smraw + SA_KH), kLb = smem_u32(smraw + SA_KL);
    const uint32_t vHb = smem_u32(smraw + SA_VH), vLb = smem_u32(smraw + SA_VL);

    for (int c = 0; c < 8; c++) {
        __syncthreads();
        stage64(g_K + ((size_t)b * N_ + c * 64) * 128, smraw + SA_KH, smraw + SA_KL, tid, 1.f);
        stage64(g_V + ((size_t)b * N_ + c * 64) * 128, smraw + SA_VH, smraw + SA_VL, tid, 1.f);
        {
            const float* Mg = mask + ((size_t)b * N_ + n0) * N_ + c * 64;
            #pragma unroll
            for (int i = 0; i < 16; i++) {
                int f = tid + 256 * i;
                int r = f >> 6, m = f & 63;
                ms[r * 68 + m] = Mg[r * N_ + m] * LOG2E;
            }
        }
        __syncthreads();

        #pragma unroll 1
        for (int half = 0; half < 2; half++) {
            const int kb = half * 32;
            // K B-fragments
            uint32_t kbh[2][4], kbl[2][4];
            #pragma unroll
            for (int np = 0; np < 2; np++) {
                uint32_t off = off64(kb + np * 16 + jnB + ir, h * 16 + jkB);
                ldm4(kbh[np], kHb + off);
                ldm4(kbl[np], kLb + off);
            }
            // scores
            float S[4][4][4];
            #pragma unroll
            for (int a = 0; a < 4; a++)
                #pragma unroll
                for (int n = 0; n < 4; n++)
                    #pragma unroll
                    for (int q = 0; q < 4; q++) S[a][n][q] = 0.f;
            #pragma unroll
            for (int ma = 0; ma < 4; ma++)
                #pragma unroll
                for (int np = 0; np < 2; np++)
                    #pragma unroll
                    for (int t = 0; t < 2; t++) {
                        float* s = S[ma][np * 2 + t];
                        mma_bf16(s, qh[ma], kbh[np][2 * t], kbh[np][2 * t + 1]);
                        mma_bf16(s, qh[ma], kbl[np][2 * t], kbl[np][2 * t + 1]);
                        mma_bf16(s, ql[ma], kbh[np][2 * t], kbh[np][2 * t + 1]);
                    }
            // + mask (already log2-scaled)
            const int colb = kb + 2 * (lane & 3);
            #pragma unroll
            for (int ma = 0; ma < 4; ma++) {
                int r = ma * 16 + (lane >> 2);
                #pragma unroll
                for (int nt = 0; nt < 4; nt++) {
                    float2 m0 = *(float2*)&ms[r * 68 + colb + nt * 8];
                    float2 m1 = *(float2*)&ms[(r + 8) * 68 + colb + nt * 8];
                    S[ma][nt][0] += m0.x; S[ma][nt][1] += m0.y;
                    S[ma][nt][2] += m1.x; S[ma][nt][3] += m1.y;
                }
            }
            // V B-fragments (trans)
            uint32_t vbh[2][4], vbl[2][4];
            #pragma unroll
            for (int t = 0; t < 2; t++) {
                uint32_t off = off64(kb + t * 16 + (j & 1) * 8 + ir,
                                     h * 16 + (j >> 1) * 8);
                ldm4t(vbh[t], vHb + off);
                ldm4t(vbl[t], vLb + off);
            }
            // online softmax (log2 domain), per row-slot
            #pragma unroll
            for (int ma = 0; ma < 4; ma++)
                #pragma unroll
                for (int rh = 0; rh < 2; rh++) {
                    const int s_ = ma * 2 + rh;
                    float mc = -1e30f;
                    #pragma unroll
                    for (int nt = 0; nt < 4; nt++)
                        mc = fmaxf(mc, fmaxf(S[ma][nt][rh * 2], S[ma][nt][rh * 2 + 1]));
                    mc = fmaxf(mc, __shfl_xor_sync(0xffffffffu, mc, 1));
                    mc = fmaxf(mc, __shfl_xor_sync(0xffffffffu, mc, 2));
                    float mnew = fmaxf(mx[s_], mc);
                    float corr = ex2f(mx[s_] - mnew);
                    mx[s_] = mnew;
                    float ps = 0.f;
                    #pragma unroll
                    for (int nt = 0; nt < 4; nt++) {
                        float p0 = ex2f(S[ma][nt][rh * 2]     - mnew);
                        float p1 = ex2f(S[ma][nt][rh * 2 + 1] - mnew);
                        S[ma][nt][rh * 2]     = p0;
                        S[ma][nt][rh * 2 + 1] = p1;
                        ps += p0 + p1;
                    }
                    ps += __shfl_xor_sync(0xffffffffu, ps, 1);
                    ps += __shfl_xor_sync(0xffffffffu, ps, 2);
                    sml[s_] = sml[s_] * corr + ps;
                    #pragma unroll
                    for (int dt = 0; dt < 2; dt++) {
                        O[ma][dt][rh * 2]     *= corr;
                        O[ma][dt][rh * 2 + 1] *= corr;
                    }
                }
            // PV
            #pragma unroll
            for (int ma = 0; ma < 4; ma++)
                #pragma unroll
                for (int t = 0; t < 2; t++) {
                    uint32_t aPh[4], aPl[4];
                    split2(S[ma][2 * t][0],     S[ma][2 * t][1],     aPh[0], aPl[0]);
                    split2(S[ma][2 * t][2],     S[ma][2 * t][3],     aPh[1], aPl[1]);
                    split2(S[ma][2 * t + 1][0], S[ma][2 * t + 1][1], aPh[2], aPl[2]);
                    split2(S[ma][2 * t + 1][2], S[ma][2 * t + 1][3], aPh[3], aPl[3]);
                    #pragma unroll
                    for (int dt = 0; dt < 2; dt++) {
                        mma_bf16(O[ma][dt], aPh, vbh[t][2 * dt], vbh[t][2 * dt + 1]);
                        mma_bf16(O[ma][dt], aPh, vbl[t][2 * dt], vbl[t][2 * dt + 1]);
                        mma_bf16(O[ma][dt], aPl, vbh[t][2 * dt], vbh[t][2 * dt + 1]);
                    }
                }
        }
    }

    // normalize + stage attention output (overlay on Q region)
    float* outs = (float*)(smraw + SA_OUTS);
    {
        float inv[8];
        #pragma unroll
        for (int s = 0; s < 8; s++) inv[s] = __fdividef(1.f, sml[s]);
        #pragma unroll
        for (int ma = 0; ma < 4; ma++) {
            int r0 = ma * 16 + (lane >> 2);
            #pragma unroll
            for (int dt = 0; dt < 2; dt++) {
                int col = h * 16 + dt * 8 + 2 * (lane & 3);
                *(float2*)&outs[r0 * 128 + col] =
                    make_float2(O[ma][dt][0] * inv[ma * 2], O[ma][dt][1] * inv[ma * 2]);
                *(float2*)&outs[(r0 + 8) * 128 + col] =
                    make_float2(O[ma][dt][2] * inv[ma * 2 + 1], O[ma][dt][3] * inv[ma * 2 + 1]);
            }
        }
    }
    __syncthreads();   // all warps done with K/V/ms regions
    stage64(outs, smraw + SA_OH, smraw + SA_OL, tid, 1.f);
    __syncthreads();

    // output projection: mh = outs @ Wc^T + bc
    {
        const int wm = h & 1, wn = h >> 1;   // 2x32 rows, 4x32 cols
        const uint32_t oHb = smem_u32(smraw + SA_OH), oLb = smem_u32(smraw + SA_OL);
        const uint32_t wHb = smem_u32(smraw + SA_WCH), wLb = smem_u32(smraw + SA_WCL);
        float E[2][4][4];
        #pragma unroll
        for (int a = 0; a < 2; a++)
            #pragma unroll
            for (int n = 0; n < 4; n++)
                #pragma unroll
                for (int q = 0; q < 4; q++) E[a][n][q] = 0.f;

        #pragma unroll
        for (int ks = 0; ks < 8; ks++) {
            const int k0 = ks * 16;
            uint32_t ah[2][4], al[2][4];
            #pragma unroll
            for (int mt = 0; mt < 2; mt++) {
                uint32_t off = off64(wm * 32 + mt * 16 + jmA + ir, k0 + jkA);
                ldm4(ah[mt], oHb + off);
                ldm4(al[mt], oLb + off);
            }
            #pragma unroll
            for (int np = 0; np < 2; np++) {
                uint32_t off = tile_off(wn * 32 + np * 16 + jnB + ir, k0 + jkB);
                uint32_t bh[4], bl[4];
                ldm4(bh, wHb + off);
                ldm4(bl, wLb + off);
                #pragma unroll
                for (int mt = 0; mt < 2; mt++) {
                    #pragma unroll
                    for (int t = 0; t < 2; t++) {
                        float* e = E[mt][np * 2 + t];
                        mma_bf16(e, ah[mt], bh[2 * t], bh[2 * t + 1]);
                        mma_bf16(e, ah[mt], bl[2 * t], bl[2 * t + 1]);
                        mma_bf16(e, al[mt], bh[2 * t], bh[2 * t + 1]);
                    }
                }
            }
        }
        #pragma unroll
        for (int mt = 0; mt < 2; mt++) {
            int gr = b * N_ + n0 + wm * 32 + mt * 16 + (lane >> 2);
            #pragma unroll
            for (int nt = 0; nt < 4; nt++) {
                int gc = wn * 32 + nt * 8 + 2 * (lane & 3);
                float2 bb = *(float2*)&sbc[gc];
                *(float2*)&g_MH[gr * 128 + gc] =
                    make_float2(E[mt][nt][0] + bb.x, E[mt][nt][1] + bb.y);
                *(float2*)&g_MH[(gr + 8) * 128 + gc] =
                    make_float2(E[mt][nt][2] + bb.x, E[mt][nt][3] + bb.y);
            }
        }
    }
}

// =====================================================================
// Pointer logits + in-block row softmax. grid (4, 64).
// =====================================================================
__global__ __launch_bounds__(256, 1)
void pointer_tc_kernel(const float* __restrict__ enc, const float* __restrict__ mask,
                       float* __restrict__ out)
{
    char* aHc = smraw;
    char* aLc = aHc + TILE_B;
    char* bHc = aLc + TILE_B;
    char* bLc = bHc + TILE_B;
    const int tid = threadIdx.x, lane = tid & 31, wid = tid >> 5;
    const int wm = wid & 3, wn = wid >> 2;
    const int b = blockIdx.y, n0 = blockIdx.x * 128;
    const float U_SCALE = 2.f * LOG2E * 0.08838834764831845f; // 2*log2e/sqrt(128)

    stage_tile(g_MH + ((size_t)b * N_ + n0) * 128, aHc, aLc, tid);

    for (int c = 0; c < 4; c++) {
        if (c) __syncthreads();
        stage_tile(enc + ((size_t)b * N_ + c * 128) * 128, bHc, bLc, tid);
        __syncthreads();

        float acc[2][8][4];
        zero_acc(acc);
        warp_mm(smem_u32(aHc), smem_u32(aLc), smem_u32(bHc), smem_u32(bLc),
                wm, wn, lane, acc);

        #pragma unroll
        for (int ma = 0; ma < 2; ma++) {
            int r = n0 + wm * 32 + ma * 16 + (lane >> 2);
            #pragma unroll
            for (int na = 0; na < 8; na++) {
                int col = c * 128 + wn * 64 + na * 8 + (lane & 3) * 2;
                #pragma unroll
                for (int half = 0; half < 2; half++) {
                    int rr = r + half * 8;
                    const float2 mv = *(const float2*)&mask[((size_t)b * N_ + rr) * N_ + col];
                    float res[2];
                    #pragma unroll
                    for (int q = 0; q < 2; q++) {
                        float s  = acc[ma][na][half * 2 + q];
                        float u  = s * U_SCALE;
                        float e2 = ex2f(u);
                        float t  = 1.f - __fdividef(2.f, e2 + 1.f);
                        float mk = (q == 0) ? mv.x : mv.y;
                        res[q] = fmaf(10.f * LOG2E, t, mk * LOG2E);
                    }
                    *(float2*)&out[((size_t)b * N_ + rr) * N_ + col] = make_float2(res[0], res[1]);
                }
            }
        }
    }

    // in-block row softmax over the 128 rows this block just wrote
    __syncthreads();
    #pragma unroll 1
    for (int rr = 0; rr < 16; rr++) {
        float4* rp = (float4*)(out + ((size_t)b * N_ + n0 + wid * 16 + rr) * N_);
        float4 v[4];
        #pragma unroll
        for (int k = 0; k < 4; k++) v[k] = rp[lane + 32 * k];
        float mxv = -1e30f;
        #pragma unroll
        for (int k = 0; k < 4; k++)
            mxv = fmaxf(mxv, fmaxf(fmaxf(v[k].x, v[k].y), fmaxf(v[k].z, v[k].w)));
        #pragma unroll
        for (int off = 16; off >= 1; off >>= 1)
            mxv = fmaxf(mxv, __shfl_xor_sync(0xffffffffu, mxv, off));
        float sum = 0.f;
        #pragma unroll
        for (int k = 0; k < 4; k++) {
            v[k].x = ex2f(v[k].x - mxv); sum += v[k].x;
            v[k].y = ex2f(v[k].y - mxv); sum += v[k].y;
            v[k].z = ex2f(v[k].z - mxv); sum += v[k].z;
            v[k].w = ex2f(v[k].w - mxv); sum += v[k].w;
        }
        #pragma unroll
        for (int off = 16; off >= 1; off >>= 1)
            sum += __shfl_xor_sync(0xffffffffu, sum, off);
        float inv = __fdividef(1.f, sum);
        #pragma unroll
        for (int k = 0; k < 4; k++) {
            v[k].x *= inv; v[k].y *= inv; v[k].z *= inv; v[k].w *= inv;
            rp[lane + 32 * k] = v[k];
        }
    }
}

// =====================================================================
extern "C" void kernel_launch(void* const* d_in, const int* in_sizes, int n_in,
                              void* d_out, int out_size)
{
    const float* enc       = (const float*)d_in[0];
    const float* first_row = (const float*)d_in[1];
    const float* q0        = (const float*)d_in[2];
    const float* mask      = (const float*)d_in[3];
    const float* Wq0       = (const float*)d_in[4];
    const float* Wq1       = (const float*)d_in[5];
    const float* Wk        = (const float*)d_in[6];
    const float* Wv        = (const float*)d_in[7];
    const float* Wc        = (const float*)d_in[8];
    const float* bc        = (const float*)d_in[9];
    float*       out       = (float*)d_out;

    float *pK, *pV, *pQ;
    cudaGetSymbolAddress((void**)&pK, g_K);
    cudaGetSymbolAddress((void**)&pV, g_V);
    cudaGetSymbolAddress((void**)&pQ, g_Q);

    const int SMEM_T = 4 * TILE_B;   // 131072

    cudaFuncSetAttribute(gemm_tc_kernel,
                         cudaFuncAttributeMaxDynamicSharedMemorySize, SMEM_T);
    cudaFuncSetAttribute(qproj_kernel,
                         cudaFuncAttributeMaxDynamicSharedMemorySize, SMEM_T);
    cudaFuncSetAttribute(pointer_tc_kernel,
                         cudaFuncAttributeMaxDynamicSharedMemorySize, SMEM_T);
    cudaFuncSetAttribute(attn_kernel,
                         cudaFuncAttributeMaxDynamicSharedMemorySize, SMEM_ATT);

    gemm_tc_kernel<<<256, 256, SMEM_T>>>(enc, Wk, pK);
    gemm_tc_kernel<<<256, 256, SMEM_T>>>(enc, Wv, pV);
    qproj_kernel  <<<256, 256, SMEM_T>>>(first_row, q0, Wq1, Wq0, pQ);

    attn_kernel<<<dim3(8, B_), 256, SMEM_ATT>>>(mask, Wc, bc);

    pointer_tc_kernel<<<dim3(4, B_), 256, SMEM_T>>>(enc, mask, out);
}

// round 9
// speedup vs baseline: 2.4092x; 1.0826x over previous
#include <cuda_runtime.h>
#include <cuda_bf16.h>
#include <math.h>
#include <cstdint>

#define B_ 64
#define N_ 512
#define E_ 128
#define H_ 8
#define D_ 16

typedef unsigned long long u64;

extern __shared__ char smraw[];

// ---------------- scratch (no allocations allowed) ----------------
__device__ float g_MH[B_ * N_ * 128];
// pre-swizzled bf16 tile caches: [B*8 chunks][64x128 blocked SW128 tile = 16KB]
__device__ char g_KH[B_ * 8 * 16384];
__device__ char g_KL[B_ * 8 * 16384];
__device__ char g_VH[B_ * 8 * 16384];
__device__ char g_VL[B_ * 8 * 16384];
__device__ char g_QH[B_ * 8 * 16384];
__device__ char g_QL[B_ * 8 * 16384];

#define LOG2E 1.4426950408889634f

// ---------------- small helpers ----------------
__device__ __forceinline__ uint32_t smem_u32(const void* p) {
    uint32_t a;
    asm("{ .reg .u64 t; cvta.to.shared.u64 t, %1; cvt.u32.u64 %0, t; }"
        : "=r"(a) : "l"(p));
    return a;
}
__device__ __forceinline__ float ex2f(float x) {
    float r; asm("ex2.approx.ftz.f32 %0, %1;" : "=f"(r) : "f"(x)); return r;
}
__device__ __forceinline__ void ldm4(uint32_t* r, uint32_t addr) {
    asm volatile("ldmatrix.sync.aligned.m8n8.x4.shared.b16 {%0,%1,%2,%3}, [%4];"
                 : "=r"(r[0]), "=r"(r[1]), "=r"(r[2]), "=r"(r[3]) : "r"(addr));
}
__device__ __forceinline__ void ldm4t(uint32_t* r, uint32_t addr) {
    asm volatile("ldmatrix.sync.aligned.m8n8.x4.trans.shared.b16 {%0,%1,%2,%3}, [%4];"
                 : "=r"(r[0]), "=r"(r[1]), "=r"(r[2]), "=r"(r[3]) : "r"(addr));
}
__device__ __forceinline__ void mma_bf16(float* d, const uint32_t* a,
                                         uint32_t b0, uint32_t b1) {
    asm volatile("mma.sync.aligned.m16n8k16.row.col.f32.bf16.bf16.f32 "
                 "{%0,%1,%2,%3}, {%4,%5,%6,%7}, {%8,%9}, {%0,%1,%2,%3};"
                 : "+f"(d[0]), "+f"(d[1]), "+f"(d[2]), "+f"(d[3])
                 : "r"(a[0]), "r"(a[1]), "r"(a[2]), "r"(a[3]), "r"(b0), "r"(b1));
}

// Byte offset of (row, k) in a 128x128-bf16 blocked SW128 tile
__device__ __forceinline__ uint32_t tile_off(int row, int k) {
    uint32_t off = (uint32_t)((((k >> 6) * 16 + (row >> 3)) * 1024)
                              + (row & 7) * 128 + (k & 63) * 2);
    return off ^ ((off >> 3) & 0x70);
}
// Byte offset of (row, k) in a 64x128-bf16 blocked SW128 tile
__device__ __forceinline__ uint32_t off64(int row, int k) {
    uint32_t off = (uint32_t)((((k >> 6) * 8 + (row >> 3)) * 1024)
                              + (row & 7) * 128 + (k & 63) * 2);
    return off ^ ((off >> 3) & 0x70);
}

__device__ __forceinline__ uint32_t pack_bf16(float a, float b) {
    __nv_bfloat16 ba = __float2bfloat16(a), bb = __float2bfloat16(b);
    return (uint32_t)*(unsigned short*)&ba | ((uint32_t)*(unsigned short*)&bb << 16);
}
__device__ __forceinline__ void split2(float x, float y, uint32_t& hi, uint32_t& lo) {
    __nv_bfloat16 bx = __float2bfloat16(x), by = __float2bfloat16(y);
    hi = (uint32_t)*(unsigned short*)&bx | ((uint32_t)*(unsigned short*)&by << 16);
    lo = pack_bf16(x - __bfloat162float(bx), y - __bfloat162float(by));
}

// Stage a 128x128 fp32 row-major tile into swizzled bf16 hi/lo tiles (32KB each)
__device__ __forceinline__ void stage_tile(const float* __restrict__ src,
                                           char* dh, char* dl, int tid) {
    const float4* s4 = (const float4*)src;
    #pragma unroll
    for (int i = 0; i < 16; i++) {
        int f = tid + 256 * i;
        int row = f >> 5, k4 = (f & 31) << 2;
        float4 v = s4[f];
        uint2 hi, lo;
        split2(v.x, v.y, hi.x, lo.x);
        split2(v.z, v.w, hi.y, lo.y);
        uint32_t o = tile_off(row, k4);
        *(uint2*)(dh + o) = hi;
        *(uint2*)(dl + o) = lo;
    }
}
// Stage a 64x128 fp32 tile into swizzled bf16 hi/lo (16KB each), scaled
__device__ __forceinline__ void stage64(const float* __restrict__ src,
                                        char* dh, char* dl, int tid, float scale) {
    const float4* s4 = (const float4*)src;
    #pragma unroll
    for (int i = 0; i < 8; i++) {
        int f = tid + 256 * i;
        int row = f >> 5, k4 = (f & 31) << 2;
        float4 v = s4[f];
        v.x *= scale; v.y *= scale; v.z *= scale; v.w *= scale;
        uint2 hi, lo;
        split2(v.x, v.y, hi.x, lo.x);
        split2(v.z, v.w, hi.y, lo.y);
        uint32_t o = off64(row, k4);
        *(uint2*)(dh + o) = hi;
        *(uint2*)(dl + o) = lo;
    }
}

#define TILE_B 32768

// ---------------------------------------------------------------------
// Warp computes its 32x64 piece of A[128x128] @ W[128x128]^T (bf16x3).
// ---------------------------------------------------------------------
__device__ __forceinline__ void warp_mm(uint32_t aH, uint32_t aL,
                                        uint32_t bH, uint32_t bL,
                                        int wm, int wn, int lane,
                                        float (*acc)[8][4])
{
    const int ir = lane & 7, j = lane >> 3;
    const int jmA = (j & 1) * 8, jkA = (j >> 1) * 8;
    const int jnB = (j >> 1) * 8, jkB = (j & 1) * 8;

    #pragma unroll
    for (int ks = 0; ks < 8; ks++) {
        const int k0 = ks * 16;
        uint32_t ah[2][4], al[2][4];
        #pragma unroll
        for (int ma = 0; ma < 2; ma++) {
            uint32_t off = tile_off(wm * 32 + ma * 16 + jmA + ir, k0 + jkA);
            ldm4(ah[ma], aH + off);
            ldm4(al[ma], aL + off);
        }
        #pragma unroll
        for (int np = 0; np < 4; np++) {
            uint32_t off = tile_off(wn * 64 + np * 16 + jnB + ir, k0 + jkB);
            uint32_t bh[4], bl[4];
            ldm4(bh, bH + off);
            ldm4(bl, bL + off);
            #pragma unroll
            for (int ma = 0; ma < 2; ma++) {
                mma_bf16(acc[ma][2 * np],     ah[ma], bh[0], bh[1]);
                mma_bf16(acc[ma][2 * np],     ah[ma], bl[0], bl[1]);
                mma_bf16(acc[ma][2 * np],     al[ma], bh[0], bh[1]);
                mma_bf16(acc[ma][2 * np + 1], ah[ma], bh[2], bh[3]);
                mma_bf16(acc[ma][2 * np + 1], ah[ma], bl[2], bl[3]);
                mma_bf16(acc[ma][2 * np + 1], al[ma], bh[2], bh[3]);
            }
        }
    }
}

__device__ __forceinline__ void zero_acc(float (*acc)[8][4]) {
    #pragma unroll
    for (int i = 0; i < 2; i++)
        #pragma unroll
        for (int j = 0; j < 8; j++)
            #pragma unroll
            for (int q = 0; q < 4; q++) acc[i][j][q] = 0.f;
}

// Write one (row, col-pair) of a projection result into a 64-row chunked
// hi/lo bf16 tile cache in global memory.
__device__ __forceinline__ void wtile(char* dh, char* dl, int nglob, int col,
                                      float v0, float v1, float scale) {
    int b = nglob >> 9, n = nglob & 511;
    size_t base = (size_t)((b << 3) + (n >> 6)) * 16384;
    uint32_t hi, lo;
    split2(v0 * scale, v1 * scale, hi, lo);
    uint32_t o = off64(n & 63, col);
    *(uint32_t*)(dh + base + o) = hi;
    *(uint32_t*)(dl + base + o) = lo;
}

// =====================================================================
// Projection -> swizzled tile cache: tiles = (A[row0:+128,:] @ W^T) * scale
// =====================================================================
__global__ __launch_bounds__(256, 1)
void proj_tile_kernel(const float* __restrict__ A, const float* __restrict__ W,
                      char* __restrict__ tH, char* __restrict__ tL, float scale)
{
    char* aHc = smraw;
    char* aLc = aHc + TILE_B;
    char* bHc = aLc + TILE_B;
    char* bLc = bHc + TILE_B;
    const int tid = threadIdx.x, lane = tid & 31, wid = tid >> 5;
    const int wm = wid & 3, wn = wid >> 2;
    const int row0 = blockIdx.x * 128;

    stage_tile(A + (size_t)row0 * 128, aHc, aLc, tid);
    stage_tile(W, bHc, bLc, tid);
    __syncthreads();

    float acc[2][8][4];
    zero_acc(acc);
    warp_mm(smem_u32(aHc), smem_u32(aLc), smem_u32(bHc), smem_u32(bLc),
            wm, wn, lane, acc);

    #pragma unroll
    for (int ma = 0; ma < 2; ma++) {
        int r = row0 + wm * 32 + ma * 16 + (lane >> 2);
        #pragma unroll
        for (int na = 0; na < 8; na++) {
            int c = wn * 64 + na * 8 + (lane & 3) * 2;
            wtile(tH, tL, r,     c, acc[ma][na][0], acc[ma][na][1], scale);
            wtile(tH, tL, r + 8, c, acc[ma][na][2], acc[ma][na][3], scale);
        }
    }
}

// =====================================================================
// Q projection -> tile cache: (fr@Wq1^T + q0@Wq0^T) * 0.25*log2e
// =====================================================================
__global__ __launch_bounds__(256, 1)
void qproj_kernel(const float* __restrict__ fr, const float* __restrict__ q0,
                  const float* __restrict__ Wq1, const float* __restrict__ Wq0)
{
    char* aHc = smraw;
    char* aLc = aHc + TILE_B;
    char* bHc = aLc + TILE_B;
    char* bLc = bHc + TILE_B;
    const int tid = threadIdx.x, lane = tid & 31, wid = tid >> 5;
    const int wm = wid & 3, wn = wid >> 2;
    const int row0 = blockIdx.x * 128;

    float acc[2][8][4];
    zero_acc(acc);

    stage_tile(fr + (size_t)row0 * 128, aHc, aLc, tid);
    stage_tile(Wq1, bHc, bLc, tid);
    __syncthreads();
    warp_mm(smem_u32(aHc), smem_u32(aLc), smem_u32(bHc), smem_u32(bLc),
            wm, wn, lane, acc);
    __syncthreads();

    stage_tile(q0 + (size_t)row0 * 128, aHc, aLc, tid);
    stage_tile(Wq0, bHc, bLc, tid);
    __syncthreads();
    warp_mm(smem_u32(aHc), smem_u32(aLc), smem_u32(bHc), smem_u32(bLc),
            wm, wn, lane, acc);

    const float qs = 0.25f * LOG2E;
    #pragma unroll
    for (int ma = 0; ma < 2; ma++) {
        int r = row0 + wm * 32 + ma * 16 + (lane >> 2);
        #pragma unroll
        for (int na = 0; na < 8; na++) {
            int c = wn * 64 + na * 8 + (lane & 3) * 2;
            wtile(g_QH, g_QL, r,     c, acc[ma][na][0], acc[ma][na][1], qs);
            wtile(g_QH, g_QL, r + 8, c, acc[ma][na][2], acc[ma][na][3], qs);
        }
    }
}

// =====================================================================
// Flash attention (bf16x3 HMMA, static-max softmax) + output projection.
// grid (8, 64). 8 warps, warp = head; 64 q-rows; 8 chunks x 64 keys.
// =====================================================================
#define SA_QH   0
#define SA_QL   16384
#define SA_KH   32768
#define SA_KL   49152
#define SA_VH   65536
#define SA_VL   81920
#define SA_WCH  98304
#define SA_WCL  131072
#define SA_MS   163840    // 64*68 floats
#define SA_BC   181248    // 128 floats
#define SA_OUTS 0         // overlay (epilogue): 64*128 fp32
#define SA_OH   32768     // overlay (epilogue)
#define SA_OL   49152
#define SMEM_ATT (181248 + 512)

__global__ __launch_bounds__(256, 1)
void attn_kernel(const float* __restrict__ mask, const float* __restrict__ Wc,
                 const float* __restrict__ bc)
{
    const int tid = threadIdx.x, lane = tid & 31, h = tid >> 5;
    const int b = blockIdx.y, n0 = blockIdx.x * 64;
    const int ir = lane & 7, j = lane >> 3;
    const int jmA = (j & 1) * 8, jkA = (j >> 1) * 8;
    const int jnB = (j >> 1) * 8, jkB = (j & 1) * 8;
    float* ms  = (float*)(smraw + SA_MS);
    float* sbc = (float*)(smraw + SA_BC);

    // copy pre-swizzled Q tile (hi/lo), stage Wc + bc
    {
        const size_t qbase = (size_t)((b << 3) + (n0 >> 6)) * 16384;
        uint4* dq0 = (uint4*)(smraw + SA_QH);
        uint4* dq1 = (uint4*)(smraw + SA_QL);
        const uint4* sq0 = (const uint4*)(g_QH + qbase);
        const uint4* sq1 = (const uint4*)(g_QL + qbase);
        #pragma unroll
        for (int i = 0; i < 4; i++) {
            dq0[tid + 256 * i] = sq0[tid + 256 * i];
            dq1[tid + 256 * i] = sq1[tid + 256 * i];
        }
    }
    stage_tile(Wc, smraw + SA_WCH, smraw + SA_WCL, tid);
    if (tid < 128) sbc[tid] = bc[tid];
    __syncthreads();

    // Q fragments (A operand), hi/lo
    uint32_t qh[4][4], ql[4][4];
    {
        uint32_t qb = smem_u32(smraw + SA_QH), qlb = smem_u32(smraw + SA_QL);
        #pragma unroll
        for (int ma = 0; ma < 4; ma++) {
            uint32_t off = off64(ma * 16 + jmA + ir, h * 16 + jkA);
            ldm4(qh[ma], qb + off);
            ldm4(ql[ma], qlb + off);
        }
    }

    float O[4][2][4];
    #pragma unroll
    for (int a = 0; a < 4; a++)
        #pragma unroll
        for (int d = 0; d < 2; d++)
            #pragma unroll
            for (int q = 0; q < 4; q++) O[a][d][q] = 0.f;
    float rs[8];
    #pragma unroll
    for (int s = 0; s < 8; s++) rs[s] = 0.f;

    const uint32_t kHb = smem_u32(smraw + SA_KH), kLb = smem_u32(smraw + SA_KL);
    const uint32_t vHb = smem_u32(smraw + SA_VH), vLb = smem_u32(smraw + SA_VL);

    for (int c = 0; c < 8; c++) {
        __syncthreads();
        {
            const size_t tb = (size_t)((b << 3) + c) * 16384;
            uint4* dk0 = (uint4*)(smraw + SA_KH);
            uint4* dk1 = (uint4*)(smraw + SA_KL);
            uint4* dv0 = (uint4*)(smraw + SA_VH);
            uint4* dv1 = (uint4*)(smraw + SA_VL);
            const uint4* sk0 = (const uint4*)(g_KH + tb);
            const uint4* sk1 = (const uint4*)(g_KL + tb);
            const uint4* sv0 = (const uint4*)(g_VH + tb);
            const uint4* sv1 = (const uint4*)(g_VL + tb);
            #pragma unroll
            for (int i = 0; i < 4; i++) {
                dk0[tid + 256 * i] = sk0[tid + 256 * i];
                dk1[tid + 256 * i] = sk1[tid + 256 * i];
                dv0[tid + 256 * i] = sv0[tid + 256 * i];
                dv1[tid + 256 * i] = sv1[tid + 256 * i];
            }
            const float* Mg = mask + ((size_t)b * N_ + n0) * N_ + c * 64;
            #pragma unroll
            for (int i = 0; i < 16; i++) {
                int f = tid + 256 * i;
                int r = f >> 6, m = f & 63;
                ms[r * 68 + m] = Mg[r * N_ + m] * LOG2E;
            }
        }
        __syncthreads();

        #pragma unroll 1
        for (int half = 0; half < 2; half++) {
            const int kb = half * 32;
            uint32_t kbh[2][4], kbl[2][4];
            #pragma unroll
            for (int np = 0; np < 2; np++) {
                uint32_t off = off64(kb + np * 16 + jnB + ir, h * 16 + jkB);
                ldm4(kbh[np], kHb + off);
                ldm4(kbl[np], kLb + off);
            }
            uint32_t vbh[2][4], vbl[2][4];
            #pragma unroll
            for (int t = 0; t < 2; t++) {
                uint32_t off = off64(kb + t * 16 + (j & 1) * 8 + ir,
                                     h * 16 + (j >> 1) * 8);
                ldm4t(vbh[t], vHb + off);
                ldm4t(vbl[t], vLb + off);
            }
            const int colb = kb + 2 * (lane & 3);

            #pragma unroll
            for (int ma = 0; ma < 4; ma++) {
                float S[4][4];
                #pragma unroll
                for (int n = 0; n < 4; n++)
                    #pragma unroll
                    for (int q = 0; q < 4; q++) S[n][q] = 0.f;
                #pragma unroll
                for (int np = 0; np < 2; np++)
                    #pragma unroll
                    for (int t = 0; t < 2; t++) {
                        float* s = S[np * 2 + t];
                        mma_bf16(s, qh[ma], kbh[np][2 * t], kbh[np][2 * t + 1]);
                        mma_bf16(s, qh[ma], kbl[np][2 * t], kbl[np][2 * t + 1]);
                        mma_bf16(s, ql[ma], kbh[np][2 * t], kbh[np][2 * t + 1]);
                    }
                // + mask (log2-scaled), then exp2 (static max: logits bounded)
                const int r = ma * 16 + (lane >> 2);
                float ps0 = 0.f, ps1 = 0.f;
                #pragma unroll
                for (int nt = 0; nt < 4; nt++) {
                    float2 m0 = *(float2*)&ms[r * 68 + colb + nt * 8];
                    float2 m1 = *(float2*)&ms[(r + 8) * 68 + colb + nt * 8];
                    S[nt][0] = ex2f(S[nt][0] + m0.x);
                    S[nt][1] = ex2f(S[nt][1] + m0.y);
                    S[nt][2] = ex2f(S[nt][2] + m1.x);
                    S[nt][3] = ex2f(S[nt][3] + m1.y);
                    ps0 += S[nt][0] + S[nt][1];
                    ps1 += S[nt][2] + S[nt][3];
                }
                rs[ma * 2]     += ps0;
                rs[ma * 2 + 1] += ps1;
                // PV
                #pragma unroll
                for (int t = 0; t < 2; t++) {
                    uint32_t aPh[4], aPl[4];
                    split2(S[2 * t][0],     S[2 * t][1],     aPh[0], aPl[0]);
                    split2(S[2 * t][2],     S[2 * t][3],     aPh[1], aPl[1]);
                    split2(S[2 * t + 1][0], S[2 * t + 1][1], aPh[2], aPl[2]);
                    split2(S[2 * t + 1][2], S[2 * t + 1][3], aPh[3], aPl[3]);
                    #pragma unroll
                    for (int dt = 0; dt < 2; dt++) {
                        mma_bf16(O[ma][dt], aPh, vbh[t][2 * dt], vbh[t][2 * dt + 1]);
                        mma_bf16(O[ma][dt], aPh, vbl[t][2 * dt], vbl[t][2 * dt + 1]);
                        mma_bf16(O[ma][dt], aPl, vbh[t][2 * dt], vbh[t][2 * dt + 1]);
                    }
                }
            }
        }
    }

    // row sums: reduce partials across the 4 lanes of each row quad
    float inv[8];
    #pragma unroll
    for (int s = 0; s < 8; s++) {
        float t = rs[s];
        t += __shfl_xor_sync(0xffffffffu, t, 1);
        t += __shfl_xor_sync(0xffffffffu, t, 2);
        inv[s] = __fdividef(1.f, t);
    }

    // normalize + stage attention output (overlay on Q region)
    float* outs = (float*)(smraw + SA_OUTS);
    #pragma unroll
    for (int ma = 0; ma < 4; ma++) {
        int r0 = ma * 16 + (lane >> 2);
        #pragma unroll
        for (int dt = 0; dt < 2; dt++) {
            int col = h * 16 + dt * 8 + 2 * (lane & 3);
            *(float2*)&outs[r0 * 128 + col] =
                make_float2(O[ma][dt][0] * inv[ma * 2], O[ma][dt][1] * inv[ma * 2]);
            *(float2*)&outs[(r0 + 8) * 128 + col] =
                make_float2(O[ma][dt][2] * inv[ma * 2 + 1], O[ma][dt][3] * inv[ma * 2 + 1]);
        }
    }
    __syncthreads();   // all warps done with K/V regions
    stage64(outs, smraw + SA_OH, smraw + SA_OL, tid, 1.f);
    __syncthreads();

    // output projection: mh = outs @ Wc^T + bc -> g_MH
    {
        const int wm = h & 1, wn = h >> 1;   // 2x32 rows, 4x32 cols
        const uint32_t oHb = smem_u32(smraw + SA_OH), oLb = smem_u32(smraw + SA_OL);
        const uint32_t wHb = smem_u32(smraw + SA_WCH), wLb = smem_u32(smraw + SA_WCL);
        float E[2][4][4];
        #pragma unroll
        for (int a = 0; a < 2; a++)
            #pragma unroll
            for (int n = 0; n < 4; n++)
                #pragma unroll
                for (int q = 0; q < 4; q++) E[a][n][q] = 0.f;

        #pragma unroll
        for (int ks = 0; ks < 8; ks++) {
            const int k0 = ks * 16;
            uint32_t ah[2][4], al[2][4];
            #pragma unroll
            for (int mt = 0; mt < 2; mt++) {
                uint32_t off = off64(wm * 32 + mt * 16 + jmA + ir, k0 + jkA);
                ldm4(ah[mt], oHb + off);
                ldm4(al[mt], oLb + off);
            }
            #pragma unroll
            for (int np = 0; np < 2; np++) {
                uint32_t off = tile_off(wn * 32 + np * 16 + jnB + ir, k0 + jkB);
                uint32_t bh[4], bl[4];
                ldm4(bh, wHb + off);
                ldm4(bl, wLb + off);
                #pragma unroll
                for (int mt = 0; mt < 2; mt++) {
                    #pragma unroll
                    for (int t = 0; t < 2; t++) {
                        float* e = E[mt][np * 2 + t];
                        mma_bf16(e, ah[mt], bh[2 * t], bh[2 * t + 1]);
                        mma_bf16(e, ah[mt], bl[2 * t], bl[2 * t + 1]);
                        mma_bf16(e, al[mt], bh[2 * t], bh[2 * t + 1]);
                    }
                }
            }
        }
        #pragma unroll
        for (int mt = 0; mt < 2; mt++) {
            int gr = b * N_ + n0 + wm * 32 + mt * 16 + (lane >> 2);
            #pragma unroll
            for (int nt = 0; nt < 4; nt++) {
                int gc = wn * 32 + nt * 8 + 2 * (lane & 3);
                float2 bb = *(float2*)&sbc[gc];
                *(float2*)&g_MH[(size_t)gr * 128 + gc] =
                    make_float2(E[mt][nt][0] + bb.x, E[mt][nt][1] + bb.y);
                *(float2*)&g_MH[(size_t)(gr + 8) * 128 + gc] =
                    make_float2(E[mt][nt][2] + bb.x, E[mt][nt][3] + bb.y);
            }
        }
    }
}

// =====================================================================
// Pointer logits + in-block row softmax. grid (4, 64).
// =====================================================================
__global__ __launch_bounds__(256, 1)
void pointer_tc_kernel(const float* __restrict__ enc, const float* __restrict__ mask,
                       float* __restrict__ out)
{
    char* aHc = smraw;
    char* aLc = aHc + TILE_B;
    char* bHc = aLc + TILE_B;
    char* bLc = bHc + TILE_B;
    const int tid = threadIdx.x, lane = tid & 31, wid = tid >> 5;
    const int wm = wid & 3, wn = wid >> 2;
    const int b = blockIdx.y, n0 = blockIdx.x * 128;
    const float U_SCALE = 2.f * LOG2E * 0.08838834764831845f; // 2*log2e/sqrt(128)

    stage_tile(g_MH + ((size_t)b * N_ + n0) * 128, aHc, aLc, tid);

    for (int c = 0; c < 4; c++) {
        if (c) __syncthreads();
        stage_tile(enc + ((size_t)b * N_ + c * 128) * 128, bHc, bLc, tid);
        __syncthreads();

        float acc[2][8][4];
        zero_acc(acc);
        warp_mm(smem_u32(aHc), smem_u32(aLc), smem_u32(bHc), smem_u32(bLc),
                wm, wn, lane, acc);

        #pragma unroll
        for (int ma = 0; ma < 2; ma++) {
            int r = n0 + wm * 32 + ma * 16 + (lane >> 2);
            #pragma unroll
            for (int na = 0; na < 8; na++) {
                int col = c * 128 + wn * 64 + na * 8 + (lane & 3) * 2;
                #pragma unroll
                for (int half = 0; half < 2; half++) {
                    int rr = r + half * 8;
                    const float2 mv = *(const float2*)&mask[((size_t)b * N_ + rr) * N_ + col];
                    float res[2];
                    #pragma unroll
                    for (int q = 0; q < 2; q++) {
                        float s  = acc[ma][na][half * 2 + q];
                        float u  = s * U_SCALE;
                        float e2 = ex2f(u);
                        float t  = 1.f - __fdividef(2.f, e2 + 1.f);
                        float mk = (q == 0) ? mv.x : mv.y;
                        res[q] = fmaf(10.f * LOG2E, t, mk * LOG2E);
                    }
                    *(float2*)&out[((size_t)b * N_ + rr) * N_ + col] = make_float2(res[0], res[1]);
                }
            }
        }
    }

    // in-block row softmax over the 128 rows this block just wrote
    __syncthreads();
    #pragma unroll 1
    for (int rr = 0; rr < 16; rr++) {
        float4* rp = (float4*)(out + ((size_t)b * N_ + n0 + wid * 16 + rr) * N_);
        float4 v[4];
        #pragma unroll
        for (int k = 0; k < 4; k++) v[k] = rp[lane + 32 * k];
        float mxv = -1e30f;
        #pragma unroll
        for (int k = 0; k < 4; k++)
            mxv = fmaxf(mxv, fmaxf(fmaxf(v[k].x, v[k].y), fmaxf(v[k].z, v[k].w)));
        #pragma unroll
        for (int off = 16; off >= 1; off >>= 1)
            mxv = fmaxf(mxv, __shfl_xor_sync(0xffffffffu, mxv, off));
        float sum = 0.f;
        #pragma unroll
        for (int k = 0; k < 4; k++) {
            v[k].x = ex2f(v[k].x - mxv); sum += v[k].x;
            v[k].y = ex2f(v[k].y - mxv); sum += v[k].y;
            v[k].z = ex2f(v[k].z - mxv); sum += v[k].z;
            v[k].w = ex2f(v[k].w - mxv); sum += v[k].w;
        }
        #pragma unroll
        for (int off = 16; off >= 1; off >>= 1)
            sum += __shfl_xor_sync(0xffffffffu, sum, off);
        float inv = __fdividef(1.f, sum);
        #pragma unroll
        for (int k = 0; k < 4; k++) {
            v[k].x *= inv; v[k].y *= inv; v[k].z *= inv; v[k].w *= inv;
            rp[lane + 32 * k] = v[k];
        }
    }
}

// =====================================================================
extern "C" void kernel_launch(void* const* d_in, const int* in_sizes, int n_in,
                              void* d_out, int out_size)
{
    const float* enc       = (const float*)d_in[0];
    const float* first_row = (const float*)d_in[1];
    const float* q0        = (const float*)d_in[2];
    const float* mask      = (const float*)d_in[3];
    const float* Wq0       = (const float*)d_in[4];
    const float* Wq1       = (const float*)d_in[5];
    const float* Wk        = (const float*)d_in[6];
    const float* Wv        = (const float*)d_in[7];
    const float* Wc        = (const float*)d_in[8];
    const float* bc        = (const float*)d_in[9];
    float*       out       = (float*)d_out;

    char *pKH, *pKL, *pVH, *pVL;
    cudaGetSymbolAddress((void**)&pKH, g_KH);
    cudaGetSymbolAddress((void**)&pKL, g_KL);
    cudaGetSymbolAddress((void**)&pVH, g_VH);
    cudaGetSymbolAddress((void**)&pVL, g_VL);

    const int SMEM_T = 4 * TILE_B;   // 131072

    cudaFuncSetAttribute(proj_tile_kernel,
                         cudaFuncAttributeMaxDynamicSharedMemorySize, SMEM_T);
    cudaFuncSetAttribute(qproj_kernel,
                         cudaFuncAttributeMaxDynamicSharedMemorySize, SMEM_T);
    cudaFuncSetAttribute(pointer_tc_kernel,
                         cudaFuncAttributeMaxDynamicSharedMemorySize, SMEM_T);
    cudaFuncSetAttribute(attn_kernel,
                         cudaFuncAttributeMaxDynamicSharedMemorySize, SMEM_ATT);

    proj_tile_kernel<<<256, 256, SMEM_T>>>(enc, Wk, pKH, pKL, 1.f);
    proj_tile_kernel<<<256, 256, SMEM_T>>>(enc, Wv, pVH, pVL, 1.f);
    qproj_kernel    <<<256, 256, SMEM_T>>>(first_row, q0, Wq1, Wq0);

    attn_kernel<<<dim3(8, B_), 256, SMEM_ATT>>>(mask, Wc, bc);

    pointer_tc_kernel<<<dim3(4, B_), 256, SMEM_T>>>(enc, mask, out);
}

// round 10
// speedup vs baseline: 2.6857x; 1.1148x over previous
#include <cuda_runtime.h>
#include <cuda_bf16.h>
#include <math.h>
#include <cstdint>

#define B_ 64
#define N_ 512
#define E_ 128
#define H_ 8
#define D_ 16

typedef unsigned long long u64;

extern __shared__ char smraw[];

// ---------------- scratch (no allocations allowed) ----------------
__device__ float g_MH[B_ * N_ * 128];
// pre-swizzled bf16 tile caches: [B*8 chunks][64x128 blocked SW128 tile = 16KB]
__device__ char g_KH[B_ * 8 * 16384];
__device__ char g_KL[B_ * 8 * 16384];
__device__ char g_VH[B_ * 8 * 16384];
__device__ char g_VL[B_ * 8 * 16384];
__device__ char g_QH[B_ * 8 * 16384];
__device__ char g_QL[B_ * 8 * 16384];

#define LOG2E 1.4426950408889634f

// ---------------- small helpers ----------------
__device__ __forceinline__ uint32_t smem_u32(const void* p) {
    uint32_t a;
    asm("{ .reg .u64 t; cvta.to.shared.u64 t, %1; cvt.u32.u64 %0, t; }"
        : "=r"(a) : "l"(p));
    return a;
}
__device__ __forceinline__ float ex2f(float x) {
    float r; asm("ex2.approx.ftz.f32 %0, %1;" : "=f"(r) : "f"(x)); return r;
}
__device__ __forceinline__ void ldm4(uint32_t* r, uint32_t addr) {
    asm volatile("ldmatrix.sync.aligned.m8n8.x4.shared.b16 {%0,%1,%2,%3}, [%4];"
                 : "=r"(r[0]), "=r"(r[1]), "=r"(r[2]), "=r"(r[3]) : "r"(addr));
}
__device__ __forceinline__ void ldm4t(uint32_t* r, uint32_t addr) {
    asm volatile("ldmatrix.sync.aligned.m8n8.x4.trans.shared.b16 {%0,%1,%2,%3}, [%4];"
                 : "=r"(r[0]), "=r"(r[1]), "=r"(r[2]), "=r"(r[3]) : "r"(addr));
}
__device__ __forceinline__ void mma_bf16(float* d, const uint32_t* a,
                                         uint32_t b0, uint32_t b1) {
    asm volatile("mma.sync.aligned.m16n8k16.row.col.f32.bf16.bf16.f32 "
                 "{%0,%1,%2,%3}, {%4,%5,%6,%7}, {%8,%9}, {%0,%1,%2,%3};"
                 : "+f"(d[0]), "+f"(d[1]), "+f"(d[2]), "+f"(d[3])
                 : "r"(a[0]), "r"(a[1]), "r"(a[2]), "r"(a[3]), "r"(b0), "r"(b1));
}
__device__ __forceinline__ void cpa16(uint32_t dst, const void* src) {
    asm volatile("cp.async.cg.shared.global [%0], [%1], 16;"
                 :: "r"(dst), "l"(src) : "memory");
}
#define CP_COMMIT() asm volatile("cp.async.commit_group;" ::: "memory")
#define CP_WAIT(n)  asm volatile("cp.async.wait_group %0;" :: "n"(n) : "memory")

// Byte offset of (row, k) in a 128x128-bf16 blocked SW128 tile
__device__ __forceinline__ uint32_t tile_off(int row, int k) {
    uint32_t off = (uint32_t)((((k >> 6) * 16 + (row >> 3)) * 1024)
                              + (row & 7) * 128 + (k & 63) * 2);
    return off ^ ((off >> 3) & 0x70);
}
// Byte offset of (row, k) in a 64x128-bf16 blocked SW128 tile
__device__ __forceinline__ uint32_t off64(int row, int k) {
    uint32_t off = (uint32_t)((((k >> 6) * 8 + (row >> 3)) * 1024)
                              + (row & 7) * 128 + (k & 63) * 2);
    return off ^ ((off >> 3) & 0x70);
}

__device__ __forceinline__ uint32_t pack_bf16(float a, float b) {
    __nv_bfloat16 ba = __float2bfloat16(a), bb = __float2bfloat16(b);
    return (uint32_t)*(unsigned short*)&ba | ((uint32_t)*(unsigned short*)&bb << 16);
}
__device__ __forceinline__ void split2(float x, float y, uint32_t& hi, uint32_t& lo) {
    __nv_bfloat16 bx = __float2bfloat16(x), by = __float2bfloat16(y);
    hi = (uint32_t)*(unsigned short*)&bx | ((uint32_t)*(unsigned short*)&by << 16);
    lo = pack_bf16(x - __bfloat162float(bx), y - __bfloat162float(by));
}

// Stage a 128x128 fp32 row-major tile into swizzled bf16 hi/lo tiles (32KB each)
__device__ __forceinline__ void stage_tile(const float* __restrict__ src,
                                           char* dh, char* dl, int tid) {
    const float4* s4 = (const float4*)src;
    #pragma unroll
    for (int i = 0; i < 16; i++) {
        int f = tid + 256 * i;
        int row = f >> 5, k4 = (f & 31) << 2;
        float4 v = s4[f];
        uint2 hi, lo;
        split2(v.x, v.y, hi.x, lo.x);
        split2(v.z, v.w, hi.y, lo.y);
        uint32_t o = tile_off(row, k4);
        *(uint2*)(dh + o) = hi;
        *(uint2*)(dl + o) = lo;
    }
}
// Stage a 64x128 fp32 tile into swizzled bf16 hi/lo (16KB each)
__device__ __forceinline__ void stage64(const float* __restrict__ src,
                                        char* dh, char* dl, int tid) {
    const float4* s4 = (const float4*)src;
    #pragma unroll
    for (int i = 0; i < 8; i++) {
        int f = tid + 256 * i;
        int row = f >> 5, k4 = (f & 31) << 2;
        float4 v = s4[f];
        uint2 hi, lo;
        split2(v.x, v.y, hi.x, lo.x);
        split2(v.z, v.w, hi.y, lo.y);
        uint32_t o = off64(row, k4);
        *(uint2*)(dh + o) = hi;
        *(uint2*)(dl + o) = lo;
    }
}

#define TILE_B 32768

// ---------------------------------------------------------------------
// Warp computes its 32x64 piece of A[128x128] @ W[128x128]^T (bf16x3).
// ---------------------------------------------------------------------
__device__ __forceinline__ void warp_mm(uint32_t aH, uint32_t aL,
                                        uint32_t bH, uint32_t bL,
                                        int wm, int wn, int lane,
                                        float (*acc)[8][4])
{
    const int ir = lane & 7, j = lane >> 3;
    const int jmA = (j & 1) * 8, jkA = (j >> 1) * 8;
    const int jnB = (j >> 1) * 8, jkB = (j & 1) * 8;

    #pragma unroll
    for (int ks = 0; ks < 8; ks++) {
        const int k0 = ks * 16;
        uint32_t ah[2][4], al[2][4];
        #pragma unroll
        for (int ma = 0; ma < 2; ma++) {
            uint32_t off = tile_off(wm * 32 + ma * 16 + jmA + ir, k0 + jkA);
            ldm4(ah[ma], aH + off);
            ldm4(al[ma], aL + off);
        }
        #pragma unroll
        for (int np = 0; np < 4; np++) {
            uint32_t off = tile_off(wn * 64 + np * 16 + jnB + ir, k0 + jkB);
            uint32_t bh[4], bl[4];
            ldm4(bh, bH + off);
            ldm4(bl, bL + off);
            #pragma unroll
            for (int ma = 0; ma < 2; ma++) {
                mma_bf16(acc[ma][2 * np],     ah[ma], bh[0], bh[1]);
                mma_bf16(acc[ma][2 * np],     ah[ma], bl[0], bl[1]);
                mma_bf16(acc[ma][2 * np],     al[ma], bh[0], bh[1]);
                mma_bf16(acc[ma][2 * np + 1], ah[ma], bh[2], bh[3]);
                mma_bf16(acc[ma][2 * np + 1], ah[ma], bl[2], bl[3]);
                mma_bf16(acc[ma][2 * np + 1], al[ma], bh[2], bh[3]);
            }
        }
    }
}

__device__ __forceinline__ void zero_acc(float (*acc)[8][4]) {
    #pragma unroll
    for (int i = 0; i < 2; i++)
        #pragma unroll
        for (int j = 0; j < 8; j++)
            #pragma unroll
            for (int q = 0; q < 4; q++) acc[i][j][q] = 0.f;
}

// Write one (row, col-pair) of a projection result into a 64-row chunked
// hi/lo bf16 tile cache in global memory.
__device__ __forceinline__ void wtile(char* dh, char* dl, int nglob, int col,
                                      float v0, float v1, float scale) {
    int b = nglob >> 9, n = nglob & 511;
    size_t base = (size_t)((b << 3) + (n >> 6)) * 16384;
    uint32_t hi, lo;
    split2(v0 * scale, v1 * scale, hi, lo);
    uint32_t o = off64(n & 63, col);
    *(uint32_t*)(dh + base + o) = hi;
    *(uint32_t*)(dl + base + o) = lo;
}

// =====================================================================
// Projection -> swizzled tile cache: tiles = (A[row0:+128,:] @ W^T) * scale
// =====================================================================
__global__ __launch_bounds__(256, 1)
void proj_tile_kernel(const float* __restrict__ A, const float* __restrict__ W,
                      char* __restrict__ tH, char* __restrict__ tL, float scale)
{
    char* aHc = smraw;
    char* aLc = aHc + TILE_B;
    char* bHc = aLc + TILE_B;
    char* bLc = bHc + TILE_B;
    const int tid = threadIdx.x, lane = tid & 31, wid = tid >> 5;
    const int wm = wid & 3, wn = wid >> 2;
    const int row0 = blockIdx.x * 128;

    stage_tile(A + (size_t)row0 * 128, aHc, aLc, tid);
    stage_tile(W, bHc, bLc, tid);
    __syncthreads();

    float acc[2][8][4];
    zero_acc(acc);
    warp_mm(smem_u32(aHc), smem_u32(aLc), smem_u32(bHc), smem_u32(bLc),
            wm, wn, lane, acc);

    #pragma unroll
    for (int ma = 0; ma < 2; ma++) {
        int r = row0 + wm * 32 + ma * 16 + (lane >> 2);
        #pragma unroll
        for (int na = 0; na < 8; na++) {
            int c = wn * 64 + na * 8 + (lane & 3) * 2;
            wtile(tH, tL, r,     c, acc[ma][na][0], acc[ma][na][1], scale);
            wtile(tH, tL, r + 8, c, acc[ma][na][2], acc[ma][na][3], scale);
        }
    }
}

// =====================================================================
// Q projection -> tile cache: (fr@Wq1^T + q0@Wq0^T) * 0.25*log2e
// =====================================================================
__global__ __launch_bounds__(256, 1)
void qproj_kernel(const float* __restrict__ fr, const float* __restrict__ q0,
                  const float* __restrict__ Wq1, const float* __restrict__ Wq0)
{
    char* aHc = smraw;
    char* aLc = aHc + TILE_B;
    char* bHc = aLc + TILE_B;
    char* bLc = bHc + TILE_B;
    const int tid = threadIdx.x, lane = tid & 31, wid = tid >> 5;
    const int wm = wid & 3, wn = wid >> 2;
    const int row0 = blockIdx.x * 128;

    float acc[2][8][4];
    zero_acc(acc);

    stage_tile(fr + (size_t)row0 * 128, aHc, aLc, tid);
    stage_tile(Wq1, bHc, bLc, tid);
    __syncthreads();
    warp_mm(smem_u32(aHc), smem_u32(aLc), smem_u32(bHc), smem_u32(bLc),
            wm, wn, lane, acc);
    __syncthreads();

    stage_tile(q0 + (size_t)row0 * 128, aHc, aLc, tid);
    stage_tile(Wq0, bHc, bLc, tid);
    __syncthreads();
    warp_mm(smem_u32(aHc), smem_u32(aLc), smem_u32(bHc), smem_u32(bLc),
            wm, wn, lane, acc);

    const float qs = 0.25f * LOG2E;
    #pragma unroll
    for (int ma = 0; ma < 2; ma++) {
        int r = row0 + wm * 32 + ma * 16 + (lane >> 2);
        #pragma unroll
        for (int na = 0; na < 8; na++) {
            int c = wn * 64 + na * 8 + (lane & 3) * 2;
            wtile(g_QH, g_QL, r,     c, acc[ma][na][0], acc[ma][na][1], qs);
            wtile(g_QH, g_QL, r + 8, c, acc[ma][na][2], acc[ma][na][3], qs);
        }
    }
}

// =====================================================================
// Flash attention: cp.async double-buffered chunks, static-max softmax,
// fused output projection. grid (8, 64). warp = head; 64 q-rows.
// =====================================================================
// layout (bytes):
#define SA_QH   0
#define SA_QL   16384
#define SA_BUF  32768          // two buffers of 82944: KH,KL,VH,VL,MS(64x68 f32)
#define BUF_SZ  82944
#define BO_KH   0
#define BO_KL   16384
#define BO_VH   32768
#define BO_VL   49152
#define BO_MS   65536          // 64 rows * 272B (stride 68 floats)
#define SA_BC   (SA_BUF + 2 * BUF_SZ)       // 198656, 512B
#define SMEM_ATT (SA_BC + 512)              // 199168
// epilogue overlays (after final sync; buffers dead):
#define SA_OUTS 32768          // 64x128 fp32
#define SA_OH   65536
#define SA_OL   81920
#define SA_WCH  98304
#define SA_WCL  131072

__device__ __forceinline__ void issue_chunk(int b, int n0, int c, int bsel,
                                            const float* __restrict__ mask,
                                            uint32_t sbase, int tid)
{
    const size_t tb = (size_t)((b << 3) + c) * 16384;
    const uint32_t d = sbase + SA_BUF + bsel * BUF_SZ;
    #pragma unroll
    for (int i = 0; i < 4; i++) {
        uint32_t f16 = (uint32_t)(tid + 256 * i) * 16;   // 0..16368
        cpa16(d + BO_KH + f16, g_KH + tb + f16);
        cpa16(d + BO_KL + f16, g_KL + tb + f16);
        cpa16(d + BO_VH + f16, g_VH + tb + f16);
        cpa16(d + BO_VL + f16, g_VL + tb + f16);
    }
    const float* Mg = mask + ((size_t)b * N_ + n0) * N_ + c * 64;
    #pragma unroll
    for (int i = 0; i < 4; i++) {
        int f = tid + 256 * i;          // 0..1023 = 64 rows x 16 chunks
        int r = f >> 4, ch = f & 15;
        cpa16(d + BO_MS + (uint32_t)(r * 272 + ch * 16), Mg + (size_t)r * N_ + ch * 4);
    }
}

__global__ __launch_bounds__(256, 1)
void attn_kernel(const float* __restrict__ mask, const float* __restrict__ Wc,
                 const float* __restrict__ bc)
{
    const int tid = threadIdx.x, lane = tid & 31, h = tid >> 5;
    const int b = blockIdx.y, n0 = blockIdx.x * 64;
    const int ir = lane & 7, j = lane >> 3;
    const int jmA = (j & 1) * 8, jkA = (j >> 1) * 8;
    const int jnB = (j >> 1) * 8, jkB = (j & 1) * 8;
    const uint32_t sbase = smem_u32(smraw);
    float* sbc = (float*)(smraw + SA_BC);

    // prologue: start chunk-0 copy immediately
    issue_chunk(b, n0, 0, 0, mask, sbase, tid);
    CP_COMMIT();

    // copy pre-swizzled Q tile (hi/lo), bc
    {
        const size_t qbase = (size_t)((b << 3) + (n0 >> 6)) * 16384;
        uint4* dq0 = (uint4*)(smraw + SA_QH);
        uint4* dq1 = (uint4*)(smraw + SA_QL);
        const uint4* sq0 = (const uint4*)(g_QH + qbase);
        const uint4* sq1 = (const uint4*)(g_QL + qbase);
        #pragma unroll
        for (int i = 0; i < 4; i++) {
            dq0[tid + 256 * i] = sq0[tid + 256 * i];
            dq1[tid + 256 * i] = sq1[tid + 256 * i];
        }
    }
    if (tid < 128) sbc[tid] = bc[tid];
    __syncthreads();

    // Q fragments (A operand), hi/lo
    uint32_t qh[4][4], ql[4][4];
    {
        #pragma unroll
        for (int ma = 0; ma < 4; ma++) {
            uint32_t off = off64(ma * 16 + jmA + ir, h * 16 + jkA);
            ldm4(qh[ma], sbase + SA_QH + off);
            ldm4(ql[ma], sbase + SA_QL + off);
        }
    }

    float O[4][2][4];
    #pragma unroll
    for (int a = 0; a < 4; a++)
        #pragma unroll
        for (int d = 0; d < 2; d++)
            #pragma unroll
            for (int q = 0; q < 4; q++) O[a][d][q] = 0.f;
    float rs[8];
    #pragma unroll
    for (int s = 0; s < 8; s++) rs[s] = 0.f;

    #pragma unroll 1
    for (int c = 0; c < 8; c++) {
        if (c < 7) { issue_chunk(b, n0, c + 1, (c + 1) & 1, mask, sbase, tid); CP_COMMIT(); }
        if (c < 7) CP_WAIT(1); else CP_WAIT(0);
        __syncthreads();

        const uint32_t bb = sbase + SA_BUF + (c & 1) * BUF_SZ;
        const uint32_t kHb = bb + BO_KH, kLb = bb + BO_KL;
        const uint32_t vHb = bb + BO_VH, vLb = bb + BO_VL;
        float* ms = (float*)(smraw + SA_BUF + (c & 1) * BUF_SZ + BO_MS);

        #pragma unroll 1
        for (int half = 0; half < 2; half++) {
            const int kb = half * 32;
            uint32_t kbh[2][4], kbl[2][4];
            #pragma unroll
            for (int np = 0; np < 2; np++) {
                uint32_t off = off64(kb + np * 16 + jnB + ir, h * 16 + jkB);
                ldm4(kbh[np], kHb + off);
                ldm4(kbl[np], kLb + off);
            }
            uint32_t vbh[2][4], vbl[2][4];
            #pragma unroll
            for (int t = 0; t < 2; t++) {
                uint32_t off = off64(kb + t * 16 + (j & 1) * 8 + ir,
                                     h * 16 + (j >> 1) * 8);
                ldm4t(vbh[t], vHb + off);
                ldm4t(vbl[t], vLb + off);
            }
            const int colb = kb + 2 * (lane & 3);

            #pragma unroll
            for (int ma = 0; ma < 4; ma++) {
                float S[4][4];
                #pragma unroll
                for (int n = 0; n < 4; n++)
                    #pragma unroll
                    for (int q = 0; q < 4; q++) S[n][q] = 0.f;
                #pragma unroll
                for (int np = 0; np < 2; np++)
                    #pragma unroll
                    for (int t = 0; t < 2; t++) {
                        float* s = S[np * 2 + t];
                        mma_bf16(s, qh[ma], kbh[np][2 * t], kbh[np][2 * t + 1]);
                        mma_bf16(s, qh[ma], kbl[np][2 * t], kbl[np][2 * t + 1]);
                        mma_bf16(s, ql[ma], kbh[np][2 * t], kbh[np][2 * t + 1]);
                    }
                const int r = ma * 16 + (lane >> 2);
                float ps0 = 0.f, ps1 = 0.f;
                #pragma unroll
                for (int nt = 0; nt < 4; nt++) {
                    float2 m0 = *(float2*)&ms[r * 68 + colb + nt * 8];
                    float2 m1 = *(float2*)&ms[(r + 8) * 68 + colb + nt * 8];
                    S[nt][0] = ex2f(fmaf(m0.x, LOG2E, S[nt][0]));
                    S[nt][1] = ex2f(fmaf(m0.y, LOG2E, S[nt][1]));
                    S[nt][2] = ex2f(fmaf(m1.x, LOG2E, S[nt][2]));
                    S[nt][3] = ex2f(fmaf(m1.y, LOG2E, S[nt][3]));
                    ps0 += S[nt][0] + S[nt][1];
                    ps1 += S[nt][2] + S[nt][3];
                }
                rs[ma * 2]     += ps0;
                rs[ma * 2 + 1] += ps1;
                #pragma unroll
                for (int t = 0; t < 2; t++) {
                    uint32_t aPh[4], aPl[4];
                    split2(S[2 * t][0],     S[2 * t][1],     aPh[0], aPl[0]);
                    split2(S[2 * t][2],     S[2 * t][3],     aPh[1], aPl[1]);
                    split2(S[2 * t + 1][0], S[2 * t + 1][1], aPh[2], aPl[2]);
                    split2(S[2 * t + 1][2], S[2 * t + 1][3], aPh[3], aPl[3]);
                    #pragma unroll
                    for (int dt = 0; dt < 2; dt++) {
                        mma_bf16(O[ma][dt], aPh, vbh[t][2 * dt], vbh[t][2 * dt + 1]);
                        mma_bf16(O[ma][dt], aPh, vbl[t][2 * dt], vbl[t][2 * dt + 1]);
                        mma_bf16(O[ma][dt], aPl, vbh[t][2 * dt], vbh[t][2 * dt + 1]);
                    }
                }
            }
        }
        __syncthreads();
    }

    // row sums: reduce partials across the 4 lanes of each row quad
    float inv[8];
    #pragma unroll
    for (int s = 0; s < 8; s++) {
        float t = rs[s];
        t += __shfl_xor_sync(0xffffffffu, t, 1);
        t += __shfl_xor_sync(0xffffffffu, t, 2);
        inv[s] = __fdividef(1.f, t);
    }

    // normalize + stage attention output (overlay buf0 region)
    float* outs = (float*)(smraw + SA_OUTS);
    #pragma unroll
    for (int ma = 0; ma < 4; ma++) {
        int r0 = ma * 16 + (lane >> 2);
        #pragma unroll
        for (int dt = 0; dt < 2; dt++) {
            int col = h * 16 + dt * 8 + 2 * (lane & 3);
            *(float2*)&outs[r0 * 128 + col] =
                make_float2(O[ma][dt][0] * inv[ma * 2], O[ma][dt][1] * inv[ma * 2]);
            *(float2*)&outs[(r0 + 8) * 128 + col] =
                make_float2(O[ma][dt][2] * inv[ma * 2 + 1], O[ma][dt][3] * inv[ma * 2 + 1]);
        }
    }
    __syncthreads();
    stage64(outs, smraw + SA_OH, smraw + SA_OL, tid);
    stage_tile(Wc, smraw + SA_WCH, smraw + SA_WCL, tid);
    __syncthreads();

    // output projection: mh = outs @ Wc^T + bc -> g_MH
    {
        const int wm = h & 1, wn = h >> 1;   // 2x32 rows, 4x32 cols
        const uint32_t oHb = sbase + SA_OH, oLb = sbase + SA_OL;
        const uint32_t wHb = sbase + SA_WCH, wLb = sbase + SA_WCL;
        float E[2][4][4];
        #pragma unroll
        for (int a = 0; a < 2; a++)
            #pragma unroll
            for (int n = 0; n < 4; n++)
                #pragma unroll
                for (int q = 0; q < 4; q++) E[a][n][q] = 0.f;

        #pragma unroll
        for (int ks = 0; ks < 8; ks++) {
            const int k0 = ks * 16;
            uint32_t ah[2][4], al[2][4];
            #pragma unroll
            for (int mt = 0; mt < 2; mt++) {
                uint32_t off = off64(wm * 32 + mt * 16 + jmA + ir, k0 + jkA);
                ldm4(ah[mt], oHb + off);
                ldm4(al[mt], oLb + off);
            }
            #pragma unroll
            for (int np = 0; np < 2; np++) {
                uint32_t off = tile_off(wn * 32 + np * 16 + jnB + ir, k0 + jkB);
                uint32_t bh[4], bl[4];
                ldm4(bh, wHb + off);
                ldm4(bl, wLb + off);
                #pragma unroll
                for (int mt = 0; mt < 2; mt++) {
                    #pragma unroll
                    for (int t = 0; t < 2; t++) {
                        float* e = E[mt][np * 2 + t];
                        mma_bf16(e, ah[mt], bh[2 * t], bh[2 * t + 1]);
                        mma_bf16(e, ah[mt], bl[2 * t], bl[2 * t + 1]);
                        mma_bf16(e, al[mt], bh[2 * t], bh[2 * t + 1]);
                    }
                }
            }
        }
        #pragma unroll
        for (int mt = 0; mt < 2; mt++) {
            int gr = b * N_ + n0 + wm * 32 + mt * 16 + (lane >> 2);
            #pragma unroll
            for (int nt = 0; nt < 4; nt++) {
                int gc = wn * 32 + nt * 8 + 2 * (lane & 3);
                float2 bb2 = *(float2*)&sbc[gc];
                *(float2*)&g_MH[(size_t)gr * 128 + gc] =
                    make_float2(E[mt][nt][0] + bb2.x, E[mt][nt][1] + bb2.y);
                *(float2*)&g_MH[(size_t)(gr + 8) * 128 + gc] =
                    make_float2(E[mt][nt][2] + bb2.x, E[mt][nt][3] + bb2.y);
            }
        }
    }
}

// =====================================================================
// Pointer logits + in-block row softmax. grid (4, 64).
// =====================================================================
__global__ __launch_bounds__(256, 1)
void pointer_tc_kernel(const float* __restrict__ enc, const float* __restrict__ mask,
                       float* __restrict__ out)
{
    char* aHc = smraw;
    char* aLc = aHc + TILE_B;
    char* bHc = aLc + TILE_B;
    char* bLc = bHc + TILE_B;
    const int tid = threadIdx.x, lane = tid & 31, wid = tid >> 5;
    const int wm = wid & 3, wn = wid >> 2;
    const int b = blockIdx.y, n0 = blockIdx.x * 128;
    const float U_SCALE = 2.f * LOG2E * 0.08838834764831845f; // 2*log2e/sqrt(128)

    stage_tile(g_MH + ((size_t)b * N_ + n0) * 128, aHc, aLc, tid);

    for (int c = 0; c < 4; c++) {
        if (c) __syncthreads();
        stage_tile(enc + ((size_t)b * N_ + c * 128) * 128, bHc, bLc, tid);
        __syncthreads();

        float acc[2][8][4];
        zero_acc(acc);
        warp_mm(smem_u32(aHc), smem_u32(aLc), smem_u32(bHc), smem_u32(bLc),
                wm, wn, lane, acc);

        #pragma unroll
        for (int ma = 0; ma < 2; ma++) {
            int r = n0 + wm * 32 + ma * 16 + (lane >> 2);
            #pragma unroll
            for (int na = 0; na < 8; na++) {
                int col = c * 128 + wn * 64 + na * 8 + (lane & 3) * 2;
                #pragma unroll
                for (int half = 0; half < 2; half++) {
                    int rr = r + half * 8;
                    const float2 mv = *(const float2*)&mask[((size_t)b * N_ + rr) * N_ + col];
                    float res[2];
                    #pragma unroll
                    for (int q = 0; q < 2; q++) {
                        float s  = acc[ma][na][half * 2 + q];
                        float u  = s * U_SCALE;
                        float e2 = ex2f(u);
                        float t  = 1.f - __fdividef(2.f, e2 + 1.f);
                        float mk = (q == 0) ? mv.x : mv.y;
                        res[q] = fmaf(10.f * LOG2E, t, mk * LOG2E);
                    }
                    *(float2*)&out[((size_t)b * N_ + rr) * N_ + col] = make_float2(res[0], res[1]);
                }
            }
        }
    }

    // in-block row softmax over the 128 rows this block just wrote
    __syncthreads();
    #pragma unroll 1
    for (int rr = 0; rr < 16; rr++) {
        float4* rp = (float4*)(out + ((size_t)b * N_ + n0 + wid * 16 + rr) * N_);
        float4 v[4];
        #pragma unroll
        for (int k = 0; k < 4; k++) v[k] = rp[lane + 32 * k];
        float mxv = -1e30f;
        #pragma unroll
        for (int k = 0; k < 4; k++)
            mxv = fmaxf(mxv, fmaxf(fmaxf(v[k].x, v[k].y), fmaxf(v[k].z, v[k].w)));
        #pragma unroll
        for (int off = 16; off >= 1; off >>= 1)
            mxv = fmaxf(mxv, __shfl_xor_sync(0xffffffffu, mxv, off));
        float sum = 0.f;
        #pragma unroll
        for (int k = 0; k < 4; k++) {
            v[k].x = ex2f(v[k].x - mxv); sum += v[k].x;
            v[k].y = ex2f(v[k].y - mxv); sum += v[k].y;
            v[k].z = ex2f(v[k].z - mxv); sum += v[k].z;
            v[k].w = ex2f(v[k].w - mxv); sum += v[k].w;
        }
        #pragma unroll
        for (int off = 16; off >= 1; off >>= 1)
            sum += __shfl_xor_sync(0xffffffffu, sum, off);
        float inv = __fdividef(1.f, sum);
        #pragma unroll
        for (int k = 0; k < 4; k++) {
            v[k].x *= inv; v[k].y *= inv; v[k].z *= inv; v[k].w *= inv;
            rp[lane + 32 * k] = v[k];
        }
    }
}

// =====================================================================
extern "C" void kernel_launch(void* const* d_in, const int* in_sizes, int n_in,
                              void* d_out, int out_size)
{
    const float* enc       = (const float*)d_in[0];
    const float* first_row = (const float*)d_in[1];
    const float* q0        = (const float*)d_in[2];
    const float* mask      = (const float*)d_in[3];
    const float* Wq0       = (const float*)d_in[4];
    const float* Wq1       = (const float*)d_in[5];
    const float* Wk        = (const float*)d_in[6];
    const float* Wv        = (const float*)d_in[7];
    const float* Wc        = (const float*)d_in[8];
    const float* bc        = (const float*)d_in[9];
    float*       out       = (float*)d_out;

    char *pKH, *pKL, *pVH, *pVL;
    cudaGetSymbolAddress((void**)&pKH, g_KH);
    cudaGetSymbolAddress((void**)&pKL, g_KL);
    cudaGetSymbolAddress((void**)&pVH, g_VH);
    cudaGetSymbolAddress((void**)&pVL, g_VL);

    const int SMEM_T = 4 * TILE_B;   // 131072

    cudaFuncSetAttribute(proj_tile_kernel,
                         cudaFuncAttributeMaxDynamicSharedMemorySize, SMEM_T);
    cudaFuncSetAttribute(qproj_kernel,
                         cudaFuncAttributeMaxDynamicSharedMemorySize, SMEM_T);
    cudaFuncSetAttribute(pointer_tc_kernel,
                         cudaFuncAttributeMaxDynamicSharedMemorySize, SMEM_T);
    cudaFuncSetAttribute(attn_kernel,
                         cudaFuncAttributeMaxDynamicSharedMemorySize, SMEM_ATT);

    proj_tile_kernel<<<256, 256, SMEM_T>>>(enc, Wk, pKH, pKL, 1.f);
    proj_tile_kernel<<<256, 256, SMEM_T>>>(enc, Wv, pVH, pVL, 1.f);
    qproj_kernel    <<<256, 256, SMEM_T>>>(first_row, q0, Wq1, Wq0);

    attn_kernel<<<dim3(8, B_), 256, SMEM_ATT>>>(mask, Wc, bc);

    pointer_tc_kernel<<<dim3(4, B_), 256, SMEM_T>>>(enc, mask, out);
}